// round 1
// baseline (speedup 1.0000x reference)
#include <cuda_runtime.h>
#include <math.h>

#define BB 8
#define NN 512
#define DMODEL 1024
#define HH 16
#define DK 64

// ---- static scratch (allowed; no runtime allocation) ----
__device__ float g_q[BB*HH*NN*DK];        // 16 MB  (b,h,n,d)
__device__ float g_k[BB*HH*NN*DK];        // 16 MB
__device__ float g_v[BB*HH*NN*DK];        // 16 MB
__device__ float g_s[BB*HH*NN*NN];        // 128 MB (b,h,q,k) bias -> logits -> probs
__device__ float g_o1[BB*NN*DMODEL];      // 16 MB  (b,n,h*dv)
__device__ float g_boxf[BB*NN*6];         // cx,cy,1/w,1/h,log w,log h

// ============================================================
// box features
// ============================================================
__global__ void boxfeat_kernel(const float* __restrict__ boxes) {
    int i = blockIdx.x * blockDim.x + threadIdx.x;
    if (i >= BB*NN) return;
    float4 bx = ((const float4*)boxes)[i];
    float cx = 0.5f * (bx.x + bx.z);
    float cy = 0.5f * (bx.y + bx.w);
    float w  = bx.z - bx.x + 1.0f;
    float h  = bx.w - bx.y + 1.0f;
    float* o = &g_boxf[i*6];
    o[0] = cx; o[1] = cy;
    o[2] = 1.0f / w; o[3] = 1.0f / h;
    o[4] = __logf(w); o[5] = __logf(h);
}

// ============================================================
// geometry bias: g_s[b,h,q,k] = log(max(relu(emb . Wg[h] + bg[h]), 1e-6))
// one thread per (q,k) pair, all 16 heads in registers
// ============================================================
__global__ void __launch_bounds__(256) geom_kernel(const float* __restrict__ Wg,
                                                   const float* __restrict__ bg) {
    __shared__ float WgS[32][16];   // [freq_idx][head] sin weights
    __shared__ float WgC[32][16];   // cos weights
    __shared__ float qf[16][6];
    __shared__ float kf[16][6];
    __shared__ float bgs[16];
    int tid = threadIdx.x;
    int b  = blockIdx.z;
    int q0 = blockIdx.y * 16, k0 = blockIdx.x * 16;

    for (int t = tid; t < 512; t += 256) {
        int i = t >> 4, h = t & 15;
        WgS[i][h] = Wg[h*64 + i];
        WgC[i][h] = Wg[h*64 + 32 + i];
    }
    if (tid < 16) {
        bgs[tid] = bg[tid];
        #pragma unroll
        for (int j = 0; j < 6; j++) qf[tid][j] = g_boxf[(b*NN + q0 + tid)*6 + j];
    } else if (tid < 32) {
        int t = tid - 16;
        #pragma unroll
        for (int j = 0; j < 6; j++) kf[t][j] = g_boxf[(b*NN + k0 + t)*6 + j];
    }
    __syncthreads();

    int ty = tid >> 4, tx = tid & 15;
    float pos[4];
    pos[0] = __logf(fmaxf(fabsf(qf[ty][0] - kf[tx][0]) * qf[ty][2], 1e-3f));
    pos[1] = __logf(fmaxf(fabsf(qf[ty][1] - kf[tx][1]) * qf[ty][3], 1e-3f));
    pos[2] = qf[ty][4] - kf[tx][4];
    pos[3] = qf[ty][5] - kf[tx][5];

    float acc[16];
    #pragma unroll
    for (int h = 0; h < 16; h++) acc[h] = bgs[h];

    const float dm[8] = {1.0f, 0.42169650f, 0.17782794f, 0.07498942f,
                         0.03162278f, 0.01333521f, 0.00562341f, 0.00237137f};
    #pragma unroll
    for (int c = 0; c < 4; c++) {
        float p100 = 100.0f * pos[c];
        #pragma unroll
        for (int f = 0; f < 8; f++) {
            float s, co;
            __sincosf(p100 * dm[f], &s, &co);
            int idx = c*8 + f;
            const float4* ws = (const float4*)&WgS[idx][0];
            const float4* wc = (const float4*)&WgC[idx][0];
            #pragma unroll
            for (int hq = 0; hq < 4; hq++) {
                float4 wa = ws[hq], wb = wc[hq];
                acc[hq*4+0] = fmaf(co, wb.x, fmaf(s, wa.x, acc[hq*4+0]));
                acc[hq*4+1] = fmaf(co, wb.y, fmaf(s, wa.y, acc[hq*4+1]));
                acc[hq*4+2] = fmaf(co, wb.z, fmaf(s, wa.z, acc[hq*4+2]));
                acc[hq*4+3] = fmaf(co, wb.w, fmaf(s, wa.w, acc[hq*4+3]));
            }
        }
    }
    int q = q0 + ty, k = k0 + tx;
    #pragma unroll
    for (int h = 0; h < 16; h++)
        g_s[((b*HH + h)*NN + q)*NN + k] = __logf(fmaxf(acc[h], 1e-6f));
}

// ============================================================
// SGEMM: C[m][j] = sum_k A[m][k] * W[j][k] + bias[j]
// M=4096, K=1024, Nout=1024; 128x128x8 tiles, 256 threads, 8x8 micro
// SRC: 0 = Ain param, 1 = g_o1
// DST: 0/1/2 -> head-scattered g_q/g_k/g_v, 3 -> Cout direct
// ============================================================
template<int SRC, int DST>
__global__ void __launch_bounds__(256, 2) sgemm_kernel(const float* __restrict__ Ain,
                                                       const float* __restrict__ W,
                                                       const float* __restrict__ bias,
                                                       float* __restrict__ Cout) {
    __shared__ float As[8][128];
    __shared__ float Ws[8][128];
    const int K = DMODEL;
    const float* A = (SRC == 0) ? Ain : g_o1;
    int tid = threadIdx.x;
    int m0 = blockIdx.y * 128, n0 = blockIdx.x * 128;
    int lrow = tid >> 1;
    int lk   = (tid & 1) * 4;
    const float* Ap = A + (m0 + lrow) * K + lk;
    const float* Wp = W + (n0 + lrow) * K + lk;

    int w = tid >> 5, lane = tid & 31;
    int ty = (w & 3) * 32 + (lane & 3) * 8;   // row base
    int tx = (w >> 2) * 64 + (lane >> 2) * 8; // col base

    float acc[8][8];
    #pragma unroll
    for (int i = 0; i < 8; i++)
        #pragma unroll
        for (int j = 0; j < 8; j++) acc[i][j] = 0.0f;

    float4 av = *(const float4*)Ap;
    float4 wv = *(const float4*)Wp;
    for (int k0 = 0; k0 < K; k0 += 8) {
        As[lk+0][lrow] = av.x; As[lk+1][lrow] = av.y;
        As[lk+2][lrow] = av.z; As[lk+3][lrow] = av.w;
        Ws[lk+0][lrow] = wv.x; Ws[lk+1][lrow] = wv.y;
        Ws[lk+2][lrow] = wv.z; Ws[lk+3][lrow] = wv.w;
        __syncthreads();
        if (k0 + 8 < K) {
            av = *(const float4*)(Ap + k0 + 8);
            wv = *(const float4*)(Wp + k0 + 8);
        }
        #pragma unroll
        for (int kk = 0; kk < 8; kk++) {
            float a[8], wr[8];
            *(float4*)&a[0] = *(const float4*)&As[kk][ty];
            *(float4*)&a[4] = *(const float4*)&As[kk][ty+4];
            *(float4*)&wr[0] = *(const float4*)&Ws[kk][tx];
            *(float4*)&wr[4] = *(const float4*)&Ws[kk][tx+4];
            #pragma unroll
            for (int i = 0; i < 8; i++)
                #pragma unroll
                for (int j = 0; j < 8; j++)
                    acc[i][j] = fmaf(a[i], wr[j], acc[i][j]);
        }
        __syncthreads();
    }

    #pragma unroll
    for (int i = 0; i < 8; i++) {
        int m = m0 + ty + i;
        int bq = m >> 9, n = m & (NN-1);
        #pragma unroll
        for (int j4 = 0; j4 < 8; j4 += 4) {
            int j = n0 + tx + j4;
            float4 r;
            r.x = acc[i][j4+0] + bias[j+0];
            r.y = acc[i][j4+1] + bias[j+1];
            r.z = acc[i][j4+2] + bias[j+2];
            r.w = acc[i][j4+3] + bias[j+3];
            if (DST < 3) {
                int h = j >> 6, d = j & 63;
                float* Cp = (DST == 0) ? g_q : (DST == 1) ? g_k : g_v;
                *(float4*)&Cp[((bq*HH + h)*NN + n)*DK + d] = r;
            } else {
                *(float4*)&Cout[m*DMODEL + j] = r;
            }
        }
    }
}

// ============================================================
// logits: g_s[b,h,q,k] += (q . k) / 8    (64x64 tiles, D=64 full)
// XOR-swizzled transposed smem tiles (stride-free float4 reads)
// ============================================================
__global__ void __launch_bounds__(128) attn_logits_kernel() {
    __shared__ float Qs[64][64];
    __shared__ float Ks[64][64];
    int tid = threadIdx.x;
    int bh = blockIdx.z;
    int q0 = blockIdx.y * 64, k0 = blockIdx.x * 64;
    const float* Q  = g_q + (bh*NN + q0)*DK;
    const float* Kp = g_k + (bh*NN + k0)*DK;

    #pragma unroll
    for (int u = 0; u < 8; u++) {
        int idx = tid + u*128;
        int row = idx >> 4;
        int c4  = (idx & 15) * 4;   // also the swizzle for this 4-col group
        float4 qv = *(const float4*)(Q + row*DK + c4);
        float4 kv = *(const float4*)(Kp + row*DK + c4);
        float vq[4] = {qv.x, qv.y, qv.z, qv.w};
        float vk[4] = {kv.x, kv.y, kv.z, kv.w};
        #pragma unroll
        for (int i = 0; i < 4; i++) {
            Qs[c4+i][row ^ c4] = vq[i];
            Ks[c4+i][row ^ c4] = vk[i];
        }
    }
    __syncthreads();

    int ty = (tid >> 4) << 3;   // 8 rows
    int tx = (tid & 15) << 2;   // 4 cols
    float acc[8][4] = {};
    #pragma unroll 8
    for (int kk = 0; kk < 64; kk++) {
        int sw = kk & 60;
        float a[8], wv[4];
        int xa = ty ^ sw;
        *(float4*)&a[0] = *(const float4*)&Qs[kk][xa];
        *(float4*)&a[4] = *(const float4*)&Qs[kk][xa ^ 4];
        *(float4*)&wv[0] = *(const float4*)&Ks[kk][tx ^ sw];
        #pragma unroll
        for (int i = 0; i < 8; i++)
            #pragma unroll
            for (int j = 0; j < 4; j++)
                acc[i][j] = fmaf(a[i], wv[j], acc[i][j]);
    }

    float* Sp = g_s + (bh*NN + q0)*NN + k0;
    #pragma unroll
    for (int i = 0; i < 8; i++) {
        float4 o = *(float4*)&Sp[(ty+i)*NN + tx];
        o.x += 0.125f * acc[i][0];
        o.y += 0.125f * acc[i][1];
        o.z += 0.125f * acc[i][2];
        o.w += 0.125f * acc[i][3];
        *(float4*)&Sp[(ty+i)*NN + tx] = o;
    }
}

// ============================================================
// softmax over k (row length 512), warp per row, in-place
// ============================================================
__global__ void __launch_bounds__(256) softmax_kernel() {
    int row  = blockIdx.x * 8 + (threadIdx.x >> 5);
    int lane = threadIdx.x & 31;
    float* p = g_s + row * NN;
    float v[16];
    #pragma unroll
    for (int i = 0; i < 16; i++) v[i] = p[lane + i*32];
    float mx = v[0];
    #pragma unroll
    for (int i = 1; i < 16; i++) mx = fmaxf(mx, v[i]);
    #pragma unroll
    for (int o = 16; o; o >>= 1) mx = fmaxf(mx, __shfl_xor_sync(0xffffffffu, mx, o));
    float sum = 0.0f;
    #pragma unroll
    for (int i = 0; i < 16; i++) { v[i] = __expf(v[i] - mx); sum += v[i]; }
    #pragma unroll
    for (int o = 16; o; o >>= 1) sum += __shfl_xor_sync(0xffffffffu, sum, o);
    float inv = 1.0f / sum;
    #pragma unroll
    for (int i = 0; i < 16; i++) p[lane + i*32] = v[i] * inv;
}

// ============================================================
// O1[b, q, h*64+d] = sum_k P[b,h,q,k] * V[b,h,k,d]
// ============================================================
__global__ void __launch_bounds__(128) pv_kernel() {
    __shared__ float Ps[16][64];
    __shared__ float Vs[16][68];
    int tid = threadIdx.x;
    int bh = blockIdx.y;
    int q0 = blockIdx.x * 64;
    const float* P = g_s + (bh*NN + q0)*NN;
    const float* V = g_v + bh*NN*DK;
    int ty = (tid >> 4) << 3;
    int tx = (tid & 15) << 2;
    int b = bh >> 4, h = bh & 15;
    float acc[8][4] = {};

    for (int k0 = 0; k0 < NN; k0 += 16) {
        #pragma unroll
        for (int u = 0; u < 2; u++) {
            int idx = tid + u*128;          // 0..255
            int row = idx >> 2;             // 0..63
            int c4  = (idx & 3) * 4;        // 0,4,8,12 — swizzle key
            float4 p4 = *(const float4*)(P + row*NN + k0 + c4);
            float vp[4] = {p4.x, p4.y, p4.z, p4.w};
            #pragma unroll
            for (int i = 0; i < 4; i++)
                Ps[c4+i][row ^ c4] = vp[i];
            int vrow = idx >> 4;            // 0..15
            int vc   = (idx & 15) * 4;
            *(float4*)&Vs[vrow][vc] = *(const float4*)(V + (k0+vrow)*DK + vc);
        }
        __syncthreads();
        #pragma unroll
        for (int kk = 0; kk < 16; kk++) {
            int sw = kk & 12;
            float a[8], vv[4];
            int xa = ty ^ sw;
            *(float4*)&a[0] = *(const float4*)&Ps[kk][xa];
            *(float4*)&a[4] = *(const float4*)&Ps[kk][xa ^ 4];
            *(float4*)&vv[0] = *(const float4*)&Vs[kk][tx];
            #pragma unroll
            for (int i = 0; i < 8; i++)
                #pragma unroll
                for (int j = 0; j < 4; j++)
                    acc[i][j] = fmaf(a[i], vv[j], acc[i][j]);
        }
        __syncthreads();
    }
    #pragma unroll
    for (int i = 0; i < 8; i++)
        *(float4*)&g_o1[(b*NN + q0 + ty + i)*DMODEL + h*DK + tx] = *(float4*)&acc[i][0];
}

// ============================================================
extern "C" void kernel_launch(void* const* d_in, const int* in_sizes, int n_in,
                              void* d_out, int out_size) {
    const float* queries = (const float*)d_in[0];
    const float* keys    = (const float*)d_in[1];
    const float* values  = (const float*)d_in[2];
    const float* boxes   = (const float*)d_in[3];
    const float* Wq = (const float*)d_in[4];
    const float* bq = (const float*)d_in[5];
    const float* Wk = (const float*)d_in[6];
    const float* bk = (const float*)d_in[7];
    const float* Wv = (const float*)d_in[8];
    const float* bv = (const float*)d_in[9];
    const float* Wo = (const float*)d_in[10];
    const float* bo = (const float*)d_in[11];
    const float* Wg = (const float*)d_in[12];
    const float* bg = (const float*)d_in[13];
    float* out = (float*)d_out;

    boxfeat_kernel<<<16, 256>>>(boxes);
    geom_kernel<<<dim3(32, 32, 8), 256>>>(Wg, bg);
    sgemm_kernel<0,0><<<dim3(8, 32), 256>>>(queries, Wq, bq, nullptr);
    sgemm_kernel<0,1><<<dim3(8, 32), 256>>>(keys,    Wk, bk, nullptr);
    sgemm_kernel<0,2><<<dim3(8, 32), 256>>>(values,  Wv, bv, nullptr);
    attn_logits_kernel<<<dim3(8, 8, 128), 128>>>();
    softmax_kernel<<<8192, 256>>>();
    pv_kernel<<<dim3(8, 128), 128>>>();
    sgemm_kernel<1,3><<<dim3(8, 32), 256>>>(nullptr, Wo, bo, out);
}

// round 2
// speedup vs baseline: 1.4149x; 1.4149x over previous
#include <cuda_runtime.h>
#include <math.h>

#define BB 8
#define NN 512
#define DMODEL 1024
#define HH 16
#define DK 64
#define BH (BB*HH)

// ---- static scratch ----
__device__ float g_q[BB*HH*NN*DK];        // (b,h,n,d)
__device__ float g_k[BB*HH*NN*DK];
__device__ float g_v[BB*HH*NN*DK];
__device__ float g_s[BB*HH*NN*NN];        // bias -> logits -> probs
__device__ float g_o1[BB*NN*DMODEL];      // (b,n,h*dv)
__device__ float g_boxf[BB*NN*6];

// ---- tf32 / mma helpers ----
__device__ __forceinline__ unsigned f2tf(float f) {
    unsigned u; asm("cvt.rna.tf32.f32 %0, %1;" : "=r"(u) : "f"(f)); return u;
}
__device__ __forceinline__ void mma8(float* c, const unsigned* a, const unsigned* b) {
    asm volatile("mma.sync.aligned.m16n8k8.row.col.f32.tf32.tf32.f32 "
        "{%0,%1,%2,%3},{%4,%5,%6,%7},{%8,%9},{%0,%1,%2,%3};"
        : "+f"(c[0]), "+f"(c[1]), "+f"(c[2]), "+f"(c[3])
        : "r"(a[0]), "r"(a[1]), "r"(a[2]), "r"(a[3]), "r"(b[0]), "r"(b[1]));
}
__device__ __forceinline__ unsigned long long pack2(float x, float y) {
    unsigned long long r; asm("mov.b64 %0,{%1,%2};" : "=l"(r) : "f"(x), "f"(y)); return r;
}
__device__ __forceinline__ void unpack2(unsigned long long v, float& x, float& y) {
    asm("mov.b64 {%0,%1},%2;" : "=f"(x), "=f"(y) : "l"(v));
}
__device__ __forceinline__ unsigned long long fma2(unsigned long long a, unsigned long long b,
                                                   unsigned long long c) {
    unsigned long long d;
    asm("fma.rn.f32x2 %0,%1,%2,%3;" : "=l"(d) : "l"(a), "l"(b), "l"(c)); return d;
}

// ============================================================
// box features
// ============================================================
__global__ void boxfeat_kernel(const float* __restrict__ boxes) {
    int i = blockIdx.x * blockDim.x + threadIdx.x;
    if (i >= BB*NN) return;
    float4 bx = ((const float4*)boxes)[i];
    float cx = 0.5f * (bx.x + bx.z);
    float cy = 0.5f * (bx.y + bx.w);
    float w  = bx.z - bx.x + 1.0f;
    float h  = bx.w - bx.y + 1.0f;
    float* o = &g_boxf[i*6];
    o[0] = cx; o[1] = cy;
    o[2] = 1.0f / w; o[3] = 1.0f / h;
    o[4] = __logf(w); o[5] = __logf(h);
}

// ============================================================
// geometry bias with packed f32x2 FMA (heads in pairs)
// ============================================================
__global__ void __launch_bounds__(256) geom_kernel(const float* __restrict__ Wg,
                                                   const float* __restrict__ bg) {
    __shared__ unsigned long long WgS2[32][8];   // [freq][head-pair]
    __shared__ unsigned long long WgC2[32][8];
    __shared__ float qf[16][6];
    __shared__ float kf[16][6];
    __shared__ float bgs[16];
    int tid = threadIdx.x;
    int b  = blockIdx.z;
    int q0 = blockIdx.y * 16, k0 = blockIdx.x * 16;

    {
        int i = tid >> 3, p = tid & 7;   // 256 threads cover 32x8 exactly
        WgS2[i][p] = pack2(Wg[(2*p)*64 + i],      Wg[(2*p+1)*64 + i]);
        WgC2[i][p] = pack2(Wg[(2*p)*64 + 32 + i], Wg[(2*p+1)*64 + 32 + i]);
    }
    if (tid < 16) {
        bgs[tid] = bg[tid];
        #pragma unroll
        for (int j = 0; j < 6; j++) qf[tid][j] = g_boxf[(b*NN + q0 + tid)*6 + j];
    } else if (tid < 32) {
        int t = tid - 16;
        #pragma unroll
        for (int j = 0; j < 6; j++) kf[t][j] = g_boxf[(b*NN + k0 + t)*6 + j];
    }
    __syncthreads();

    int ty = tid >> 4, tx = tid & 15;
    float pos[4];
    pos[0] = __logf(fmaxf(fabsf(qf[ty][0] - kf[tx][0]) * qf[ty][2], 1e-3f));
    pos[1] = __logf(fmaxf(fabsf(qf[ty][1] - kf[tx][1]) * qf[ty][3], 1e-3f));
    pos[2] = qf[ty][4] - kf[tx][4];
    pos[3] = qf[ty][5] - kf[tx][5];

    unsigned long long acc2[8];
    #pragma unroll
    for (int p = 0; p < 8; p++) acc2[p] = pack2(bgs[2*p], bgs[2*p+1]);

    const float dm[8] = {1.0f, 0.42169650f, 0.17782794f, 0.07498942f,
                         0.03162278f, 0.01333521f, 0.00562341f, 0.00237137f};
    #pragma unroll
    for (int c = 0; c < 4; c++) {
        float p100 = 100.0f * pos[c];
        #pragma unroll
        for (int f = 0; f < 8; f++) {
            float s, co;
            __sincosf(p100 * dm[f], &s, &co);
            unsigned long long s2 = pack2(s, s), c2 = pack2(co, co);
            int idx = c*8 + f;
            #pragma unroll
            for (int p = 0; p < 8; p++) {
                unsigned long long t = fma2(c2, WgC2[idx][p], acc2[p]);
                acc2[p] = fma2(s2, WgS2[idx][p], t);
            }
        }
    }
    int q = q0 + ty, k = k0 + tx;
    #pragma unroll
    for (int p = 0; p < 8; p++) {
        float x, y;
        unpack2(acc2[p], x, y);
        g_s[((b*HH + 2*p  )*NN + q)*NN + k] = __logf(fmaxf(x, 1e-6f));
        g_s[((b*HH + 2*p+1)*NN + q)*NN + k] = __logf(fmaxf(y, 1e-6f));
    }
}

// ============================================================
// tf32 tensor-core GEMM: C[m][n] = sum_k A[m][k]*B[n][k] (+epilogue)
// CTA tile 128x256, K-tile 8, 256 threads = 8 warps of 64x64
// MODE: 0/1/2 -> QKV proj (scatter to g_q/g_k/g_v), 3 -> out proj,
//       4 -> attention logits (g_s += 0.125*acc), A=g_q B=g_k per bh
// ============================================================
template<int MODE>
__global__ void __launch_bounds__(256) mma_gemm_kernel(const float* __restrict__ Ain,
                                                       const float* __restrict__ Bin,
                                                       const float* __restrict__ bias,
                                                       float* __restrict__ Cout) {
    __shared__ unsigned As[2][128][12];
    __shared__ unsigned Bs[2][256][12];
    const int Kdim = (MODE == 4) ? DK : DMODEL;
    int t = threadIdx.x;
    int m0 = blockIdx.y * 128, n0 = blockIdx.x * 256;

    const float* A;
    const float* B;
    if (MODE == 4)      { int bh = blockIdx.z; A = g_q + bh*NN*DK; B = g_k + bh*NN*DK; }
    else if (MODE == 3) { A = g_o1; B = Bin; }
    else                { A = Ain;  B = Bin; }

    int arow = t >> 1, ak = (t & 1) * 4;
    const float* Ap  = A + (m0 + arow) * Kdim + ak;
    const float* Bp0 = B + (n0 + arow) * Kdim + ak;
    const float* Bp1 = Bp0 + 128 * Kdim;

    int w = t >> 5, l = t & 31;
    int wm = w & 1, wn = w >> 1;
    int mbase = wm * 64, nbase = wn * 64;

    float acc[4][8][4];
    #pragma unroll
    for (int i = 0; i < 4; i++)
        #pragma unroll
        for (int j = 0; j < 8; j++)
            #pragma unroll
            for (int k = 0; k < 4; k++) acc[i][j][k] = 0.0f;

    float4 av  = *(const float4*)Ap;
    float4 bv0 = *(const float4*)Bp0;
    float4 bv1 = *(const float4*)Bp1;
    *(uint2*)&As[0][arow][ak]       = make_uint2(f2tf(av.x),  f2tf(av.y));
    *(uint2*)&As[0][arow][ak+2]     = make_uint2(f2tf(av.z),  f2tf(av.w));
    *(uint2*)&Bs[0][arow][ak]       = make_uint2(f2tf(bv0.x), f2tf(bv0.y));
    *(uint2*)&Bs[0][arow][ak+2]     = make_uint2(f2tf(bv0.z), f2tf(bv0.w));
    *(uint2*)&Bs[0][arow+128][ak]   = make_uint2(f2tf(bv1.x), f2tf(bv1.y));
    *(uint2*)&Bs[0][arow+128][ak+2] = make_uint2(f2tf(bv1.z), f2tf(bv1.w));

    const int nkt = Kdim / 8;
    int r0 = mbase + (l >> 2), c0 = l & 3;
    #pragma unroll 1
    for (int kt = 0; kt < nkt; kt++) {
        __syncthreads();
        int buf = kt & 1;
        if (kt + 1 < nkt) {
            av  = *(const float4*)(Ap  + (kt+1)*8);
            bv0 = *(const float4*)(Bp0 + (kt+1)*8);
            bv1 = *(const float4*)(Bp1 + (kt+1)*8);
        }
        unsigned a[4][4];
        #pragma unroll
        for (int mf = 0; mf < 4; mf++) {
            a[mf][0] = As[buf][r0 + mf*16    ][c0];
            a[mf][1] = As[buf][r0 + mf*16 + 8][c0];
            a[mf][2] = As[buf][r0 + mf*16    ][c0+4];
            a[mf][3] = As[buf][r0 + mf*16 + 8][c0+4];
        }
        #pragma unroll
        for (int nf = 0; nf < 8; nf++) {
            unsigned b[2];
            int bn = nbase + nf*8 + (l >> 2);
            b[0] = Bs[buf][bn][c0];
            b[1] = Bs[buf][bn][c0+4];
            #pragma unroll
            for (int mf = 0; mf < 4; mf++) mma8(acc[mf][nf], a[mf], b);
        }
        if (kt + 1 < nkt) {
            int nb = (kt + 1) & 1;
            *(uint2*)&As[nb][arow][ak]       = make_uint2(f2tf(av.x),  f2tf(av.y));
            *(uint2*)&As[nb][arow][ak+2]     = make_uint2(f2tf(av.z),  f2tf(av.w));
            *(uint2*)&Bs[nb][arow][ak]       = make_uint2(f2tf(bv0.x), f2tf(bv0.y));
            *(uint2*)&Bs[nb][arow][ak+2]     = make_uint2(f2tf(bv0.z), f2tf(bv0.w));
            *(uint2*)&Bs[nb][arow+128][ak]   = make_uint2(f2tf(bv1.x), f2tf(bv1.y));
            *(uint2*)&Bs[nb][arow+128][ak+2] = make_uint2(f2tf(bv1.z), f2tf(bv1.w));
        }
    }

    // epilogue
    int r0g = m0 + mbase + (l >> 2);
    #pragma unroll
    for (int mf = 0; mf < 4; mf++) {
        #pragma unroll
        for (int nf = 0; nf < 8; nf++) {
            int col = n0 + nbase + nf*8 + 2*(l & 3);
            float2 b2 = make_float2(0.f, 0.f);
            if (MODE < 4) b2 = *(const float2*)(bias + col);
            #pragma unroll
            for (int rr = 0; rr < 2; rr++) {
                int row = r0g + mf*16 + rr*8;
                float v0 = acc[mf][nf][rr*2 + 0];
                float v1 = acc[mf][nf][rr*2 + 1];
                if (MODE < 3) {
                    int h = col >> 6, d = col & 63;
                    int bq = row >> 9, ntok = row & (NN-1);
                    float* dst = (MODE == 0) ? g_q : (MODE == 1) ? g_k : g_v;
                    *(float2*)&dst[((bq*HH + h)*NN + ntok)*DK + d] =
                        make_float2(v0 + b2.x, v1 + b2.y);
                } else if (MODE == 3) {
                    *(float2*)&Cout[row*DMODEL + col] = make_float2(v0 + b2.x, v1 + b2.y);
                } else {
                    float* p = g_s + (size_t)blockIdx.z*NN*NN + row*NN + col;
                    float2 o = *(float2*)p;
                    o.x += 0.125f * v0;
                    o.y += 0.125f * v1;
                    *(float2*)p = o;
                }
            }
        }
    }
}

// ============================================================
// softmax over k (512), warp per row, in-place
// ============================================================
__global__ void __launch_bounds__(256) softmax_kernel() {
    int row  = blockIdx.x * 8 + (threadIdx.x >> 5);
    int lane = threadIdx.x & 31;
    float* p = g_s + (size_t)row * NN;
    float v[16];
    #pragma unroll
    for (int i = 0; i < 16; i++) v[i] = p[lane + i*32];
    float mx = v[0];
    #pragma unroll
    for (int i = 1; i < 16; i++) mx = fmaxf(mx, v[i]);
    #pragma unroll
    for (int o = 16; o; o >>= 1) mx = fmaxf(mx, __shfl_xor_sync(0xffffffffu, mx, o));
    float sum = 0.0f;
    #pragma unroll
    for (int i = 0; i < 16; i++) { v[i] = __expf(v[i] - mx); sum += v[i]; }
    #pragma unroll
    for (int o = 16; o; o >>= 1) sum += __shfl_xor_sync(0xffffffffu, sum, o);
    float inv = 1.0f / sum;
    #pragma unroll
    for (int i = 0; i < 16; i++) p[lane + i*32] = v[i] * inv;
}

// ============================================================
// PV via tf32 mma: O1[b,q,h*64+d] = sum_k P[bh,q,k]*V[bh,k,d]
// CTA tile 256(q) x 64(d), K-tile 8, 128 threads = 4 warps of 64x64
// ============================================================
__global__ void __launch_bounds__(128) mma_pv_kernel() {
    __shared__ unsigned Ps[2][256][12];
    __shared__ unsigned Vs[2][8][72];
    int bh = blockIdx.y, q0 = blockIdx.x * 256;
    const float* P = g_s + ((size_t)bh*NN + q0) * NN;
    const float* V = g_v + (size_t)bh*NN*DK;
    int t = threadIdx.x, w = t >> 5, l = t & 31;

    int prow = t >> 1, pk = (t & 1) * 4;     // rows prow, prow+64, +128, +192
    int vrow = t >> 4, vc = (t & 15) * 4;

    float acc[4][8][4];
    #pragma unroll
    for (int i = 0; i < 4; i++)
        #pragma unroll
        for (int j = 0; j < 8; j++)
            #pragma unroll
            for (int k = 0; k < 4; k++) acc[i][j][k] = 0.0f;

    float4 pa[4];
    #pragma unroll
    for (int i = 0; i < 4; i++)
        pa[i] = *(const float4*)(P + (prow + i*64)*NN + pk);
    float4 vv = *(const float4*)(V + vrow*DK + vc);
    #pragma unroll
    for (int i = 0; i < 4; i++) {
        *(uint2*)&Ps[0][prow + i*64][pk]   = make_uint2(f2tf(pa[i].x), f2tf(pa[i].y));
        *(uint2*)&Ps[0][prow + i*64][pk+2] = make_uint2(f2tf(pa[i].z), f2tf(pa[i].w));
    }
    *(uint2*)&Vs[0][vrow][vc]   = make_uint2(f2tf(vv.x), f2tf(vv.y));
    *(uint2*)&Vs[0][vrow][vc+2] = make_uint2(f2tf(vv.z), f2tf(vv.w));

    const int nkt = NN / 8;   // 64
    int mbase = w * 64;
    int r0 = mbase + (l >> 2), c0 = l & 3;
    #pragma unroll 1
    for (int kt = 0; kt < nkt; kt++) {
        __syncthreads();
        int buf = kt & 1;
        if (kt + 1 < nkt) {
            #pragma unroll
            for (int i = 0; i < 4; i++)
                pa[i] = *(const float4*)(P + (prow + i*64)*NN + (kt+1)*8 + pk);
            vv = *(const float4*)(V + ((kt+1)*8 + vrow)*DK + vc);
        }
        unsigned a[4][4];
        #pragma unroll
        for (int mf = 0; mf < 4; mf++) {
            a[mf][0] = Ps[buf][r0 + mf*16    ][c0];
            a[mf][1] = Ps[buf][r0 + mf*16 + 8][c0];
            a[mf][2] = Ps[buf][r0 + mf*16    ][c0+4];
            a[mf][3] = Ps[buf][r0 + mf*16 + 8][c0+4];
        }
        #pragma unroll
        for (int nf = 0; nf < 8; nf++) {
            unsigned b[2];
            int bn = nf*8 + (l >> 2);
            b[0] = Vs[buf][c0  ][bn];
            b[1] = Vs[buf][c0+4][bn];
            #pragma unroll
            for (int mf = 0; mf < 4; mf++) mma8(acc[mf][nf], a[mf], b);
        }
        if (kt + 1 < nkt) {
            int nb = (kt + 1) & 1;
            #pragma unroll
            for (int i = 0; i < 4; i++) {
                *(uint2*)&Ps[nb][prow + i*64][pk]   = make_uint2(f2tf(pa[i].x), f2tf(pa[i].y));
                *(uint2*)&Ps[nb][prow + i*64][pk+2] = make_uint2(f2tf(pa[i].z), f2tf(pa[i].w));
            }
            *(uint2*)&Vs[nb][vrow][vc]   = make_uint2(f2tf(vv.x), f2tf(vv.y));
            *(uint2*)&Vs[nb][vrow][vc+2] = make_uint2(f2tf(vv.z), f2tf(vv.w));
        }
    }

    int b = bh >> 4, h = bh & 15;
    #pragma unroll
    for (int mf = 0; mf < 4; mf++) {
        #pragma unroll
        for (int nf = 0; nf < 8; nf++) {
            int col = nf*8 + 2*(l & 3);
            #pragma unroll
            for (int rr = 0; rr < 2; rr++) {
                int row = q0 + mbase + mf*16 + rr*8 + (l >> 2);
                *(float2*)&g_o1[((size_t)b*NN + row)*DMODEL + h*DK + col] =
                    make_float2(acc[mf][nf][rr*2 + 0], acc[mf][nf][rr*2 + 1]);
            }
        }
    }
}

// ============================================================
extern "C" void kernel_launch(void* const* d_in, const int* in_sizes, int n_in,
                              void* d_out, int out_size) {
    const float* queries = (const float*)d_in[0];
    const float* keys    = (const float*)d_in[1];
    const float* values  = (const float*)d_in[2];
    const float* boxes   = (const float*)d_in[3];
    const float* Wq = (const float*)d_in[4];
    const float* bq = (const float*)d_in[5];
    const float* Wk = (const float*)d_in[6];
    const float* bk = (const float*)d_in[7];
    const float* Wv = (const float*)d_in[8];
    const float* bv = (const float*)d_in[9];
    const float* Wo = (const float*)d_in[10];
    const float* bo = (const float*)d_in[11];
    const float* Wg = (const float*)d_in[12];
    const float* bg = (const float*)d_in[13];
    float* out = (float*)d_out;

    boxfeat_kernel<<<16, 256>>>(boxes);
    geom_kernel<<<dim3(32, 32, 8), 256>>>(Wg, bg);
    mma_gemm_kernel<0><<<dim3(4, 32, 1), 256>>>(queries, Wq, bq, nullptr);
    mma_gemm_kernel<1><<<dim3(4, 32, 1), 256>>>(keys,    Wk, bk, nullptr);
    mma_gemm_kernel<2><<<dim3(4, 32, 1), 256>>>(values,  Wv, bv, nullptr);
    mma_gemm_kernel<4><<<dim3(2, 4, 128), 256>>>(nullptr, nullptr, nullptr, nullptr);
    softmax_kernel<<<8192, 256>>>();
    mma_pv_kernel<<<dim3(2, 128), 128>>>();
    mma_gemm_kernel<3><<<dim3(4, 32, 1), 256>>>(nullptr, Wo, bo, out);
}

// round 5
// speedup vs baseline: 1.7765x; 1.2556x over previous
#include <cuda_runtime.h>
#include <math.h>

#define BB 8
#define NN 512
#define DMODEL 1024
#define HH 16
#define DK 64
#define SST 12

// ---- static scratch ----
__device__ float g_q[BB*HH*NN*DK];
__device__ float g_k[BB*HH*NN*DK];
__device__ float g_v[BB*HH*NN*DK];
__device__ float g_s[BB*HH*NN*NN];
__device__ float g_o1[BB*NN*DMODEL];
__device__ float g_boxf[BB*NN*6];

// ---- helpers ----
__device__ __forceinline__ unsigned f2tf(float f) {
    unsigned u; asm("cvt.rna.tf32.f32 %0, %1;" : "=r"(u) : "f"(f)); return u;
}
__device__ __forceinline__ void mma8(float* c, const unsigned* a, const unsigned* b) {
    asm volatile("mma.sync.aligned.m16n8k8.row.col.f32.tf32.tf32.f32 "
        "{%0,%1,%2,%3},{%4,%5,%6,%7},{%8,%9},{%0,%1,%2,%3};"
        : "+f"(c[0]), "+f"(c[1]), "+f"(c[2]), "+f"(c[3])
        : "r"(a[0]), "r"(a[1]), "r"(a[2]), "r"(a[3]), "r"(b[0]), "r"(b[1]));
}
__device__ __forceinline__ void cpa16(unsigned dst, const void* src) {
    asm volatile("cp.async.cg.shared.global [%0], [%1], 16;" :: "r"(dst), "l"(src));
}
__device__ __forceinline__ void cp_commit() {
    asm volatile("cp.async.commit_group;" ::: "memory");
}
__device__ __forceinline__ void cp_wait2() {
    asm volatile("cp.async.wait_group 2;" ::: "memory");
}
__device__ __forceinline__ unsigned long long pack2(float x, float y) {
    unsigned long long r; asm("mov.b64 %0,{%1,%2};" : "=l"(r) : "f"(x), "f"(y)); return r;
}
__device__ __forceinline__ void unpack2(unsigned long long v, float& x, float& y) {
    asm("mov.b64 {%0,%1},%2;" : "=f"(x), "=f"(y) : "l"(v));
}
__device__ __forceinline__ unsigned long long fma2(unsigned long long a, unsigned long long b,
                                                   unsigned long long c) {
    unsigned long long d;
    asm("fma.rn.f32x2 %0,%1,%2,%3;" : "=l"(d) : "l"(a), "l"(b), "l"(c)); return d;
}

// ============================================================
// box features
// ============================================================
__global__ void boxfeat_kernel(const float* __restrict__ boxes) {
    int i = blockIdx.x * blockDim.x + threadIdx.x;
    if (i >= BB*NN) return;
    float4 bx = ((const float4*)boxes)[i];
    float cx = 0.5f * (bx.x + bx.z);
    float cy = 0.5f * (bx.y + bx.w);
    float w  = bx.z - bx.x + 1.0f;
    float h  = bx.w - bx.y + 1.0f;
    float* o = &g_boxf[i*6];
    o[0] = cx; o[1] = cy;
    o[2] = 1.0f / w; o[3] = 1.0f / h;
    o[4] = __logf(w); o[5] = __logf(h);
}

// ============================================================
// geometry bias, packed f32x2 over head pairs
// ============================================================
__global__ void __launch_bounds__(256) geom_kernel(const float* __restrict__ Wg,
                                                   const float* __restrict__ bg) {
    __shared__ unsigned long long WgS2[32][8];
    __shared__ unsigned long long WgC2[32][8];
    __shared__ float qf[16][6];
    __shared__ float kf[16][6];
    __shared__ float bgs[16];
    int tid = threadIdx.x;
    int b  = blockIdx.z;
    int q0 = blockIdx.y * 16, k0 = blockIdx.x * 16;

    {
        int i = tid >> 3, p = tid & 7;
        WgS2[i][p] = pack2(Wg[(2*p)*64 + i],      Wg[(2*p+1)*64 + i]);
        WgC2[i][p] = pack2(Wg[(2*p)*64 + 32 + i], Wg[(2*p+1)*64 + 32 + i]);
    }
    if (tid < 16) {
        bgs[tid] = bg[tid];
        #pragma unroll
        for (int j = 0; j < 6; j++) qf[tid][j] = g_boxf[(b*NN + q0 + tid)*6 + j];
    } else if (tid < 32) {
        int t = tid - 16;
        #pragma unroll
        for (int j = 0; j < 6; j++) kf[t][j] = g_boxf[(b*NN + k0 + t)*6 + j];
    }
    __syncthreads();

    int ty = tid >> 4, tx = tid & 15;
    float pos[4];
    pos[0] = __logf(fmaxf(fabsf(qf[ty][0] - kf[tx][0]) * qf[ty][2], 1e-3f));
    pos[1] = __logf(fmaxf(fabsf(qf[ty][1] - kf[tx][1]) * qf[ty][3], 1e-3f));
    pos[2] = qf[ty][4] - kf[tx][4];
    pos[3] = qf[ty][5] - kf[tx][5];

    unsigned long long acc2[8];
    #pragma unroll
    for (int p = 0; p < 8; p++) acc2[p] = pack2(bgs[2*p], bgs[2*p+1]);

    const float dm[8] = {1.0f, 0.42169650f, 0.17782794f, 0.07498942f,
                         0.03162278f, 0.01333521f, 0.00562341f, 0.00237137f};
    #pragma unroll
    for (int c = 0; c < 4; c++) {
        float p100 = 100.0f * pos[c];
        #pragma unroll
        for (int f = 0; f < 8; f++) {
            float s, co;
            __sincosf(p100 * dm[f], &s, &co);
            unsigned long long s2 = pack2(s, s), c2 = pack2(co, co);
            int idx = c*8 + f;
            #pragma unroll
            for (int p = 0; p < 8; p++) {
                unsigned long long t = fma2(c2, WgC2[idx][p], acc2[p]);
                acc2[p] = fma2(s2, WgS2[idx][p], t);
            }
        }
    }
    int q = q0 + ty, k = k0 + tx;
    #pragma unroll
    for (int p = 0; p < 8; p++) {
        float x, y;
        unpack2(acc2[p], x, y);
        g_s[(((size_t)b*HH + 2*p  )*NN + q)*NN + k] = __logf(fmaxf(x, 1e-6f));
        g_s[(((size_t)b*HH + 2*p+1)*NN + q)*NN + k] = __logf(fmaxf(y, 1e-6f));
    }
}

// ============================================================
// tf32 GEMM core, 128x128 CTA tile, 8 warps of 32x64, cp.async x4
// MODE 0: QKV projections (z picks input/W/bias, scatter per head)
// MODE 1: output projection  (A=g_o1 [device-resolved], B=Wo, bias, dst=Cout)
// MODE 2: attention logits   (A=g_q, B=g_k per z=bh, g_s += 0.125*acc)
// ============================================================
template<int MODE>
__global__ void __launch_bounds__(256, 2) gemm_tc(
    const float* __restrict__ A0, const float* __restrict__ A1, const float* __restrict__ A2,
    const float* __restrict__ B0, const float* __restrict__ B1, const float* __restrict__ B2,
    const float* __restrict__ c0p, const float* __restrict__ c1p, const float* __restrict__ c2p,
    float* __restrict__ Cout)
{
    constexpr int KD  = (MODE == 2) ? DK : DMODEL;
    constexpr int NKT = KD / 8;
    __shared__ float As[4][128][SST];
    __shared__ float Bs[4][128][SST];

    int t = threadIdx.x;
    int m0 = blockIdx.y * 128, n0 = blockIdx.x * 128;
    int z = blockIdx.z;

    const float *A, *B, *bias = nullptr;
    if (MODE == 0) {
        A = (z == 0) ? A0 : (z == 1) ? A1 : A2;
        B = (z == 0) ? B0 : (z == 1) ? B1 : B2;
        bias = (z == 0) ? c0p : (z == 1) ? c1p : c2p;
    } else if (MODE == 1) {
        A = g_o1;              // device-side symbol resolution (host must NOT pass it)
        B = B0; bias = c0p;
    } else {
        A = g_q + (size_t)z*NN*DK;
        B = g_k + (size_t)z*NN*DK;
    }

    int lrow = t >> 1, lc = (t & 1) * 4;
    const float* Ap = A + (size_t)(m0 + lrow)*KD + lc;
    const float* Bp = B + (size_t)(n0 + lrow)*KD + lc;
    unsigned sa = (unsigned)__cvta_generic_to_shared(&As[0][lrow][lc]);
    unsigned sb = (unsigned)__cvta_generic_to_shared(&Bs[0][lrow][lc]);
    constexpr unsigned STB = 128u * SST * 4u;

    int w = t >> 5, l = t & 31;
    int wm = w & 3, wn = w >> 2;
    int r0  = wm*32 + (l >> 2), c0 = l & 3;
    int bn0 = wn*64 + (l >> 2);

    float acc[2][8][4];
    #pragma unroll
    for (int i = 0; i < 2; i++)
        #pragma unroll
        for (int j = 0; j < 8; j++)
            #pragma unroll
            for (int k = 0; k < 4; k++) acc[i][j][k] = 0.0f;

    #pragma unroll
    for (int p = 0; p < 3; p++) {
        if (p < NKT) {
            cpa16(sa + (p & 3)*STB, Ap + p*8);
            cpa16(sb + (p & 3)*STB, Bp + p*8);
        }
        cp_commit();
    }

    for (int kt = 0; kt < NKT; kt++) {
        cp_wait2();
        __syncthreads();
        if (kt + 3 < NKT) {
            int s = (kt + 3) & 3;
            cpa16(sa + s*STB, Ap + (kt+3)*8);
            cpa16(sb + s*STB, Bp + (kt+3)*8);
        }
        cp_commit();

        int s = kt & 3;
        unsigned a[2][4];
        #pragma unroll
        for (int mf = 0; mf < 2; mf++) {
            a[mf][0] = f2tf(As[s][r0 + mf*16    ][c0]);
            a[mf][1] = f2tf(As[s][r0 + mf*16 + 8][c0]);
            a[mf][2] = f2tf(As[s][r0 + mf*16    ][c0+4]);
            a[mf][3] = f2tf(As[s][r0 + mf*16 + 8][c0+4]);
        }
        #pragma unroll
        for (int nf = 0; nf < 8; nf++) {
            unsigned b[2];
            b[0] = f2tf(Bs[s][bn0 + nf*8][c0]);
            b[1] = f2tf(Bs[s][bn0 + nf*8][c0+4]);
            #pragma unroll
            for (int mf = 0; mf < 2; mf++) mma8(acc[mf][nf], a[mf], b);
        }
    }

    // epilogue
    #pragma unroll
    for (int mf = 0; mf < 2; mf++) {
        #pragma unroll
        for (int nf = 0; nf < 8; nf++) {
            int col = n0 + wn*64 + nf*8 + 2*(l & 3);
            float2 b2 = make_float2(0.f, 0.f);
            if (MODE < 2) b2 = *(const float2*)(bias + col);
            #pragma unroll
            for (int rr = 0; rr < 2; rr++) {
                int row = m0 + wm*32 + mf*16 + rr*8 + (l >> 2);
                float v0 = acc[mf][nf][rr*2 + 0];
                float v1 = acc[mf][nf][rr*2 + 1];
                if (MODE == 0) {
                    int h = col >> 6, d = col & 63;
                    int bq = row >> 9, ntok = row & (NN-1);
                    float* dstp = (z == 0) ? g_q : (z == 1) ? g_k : g_v;
                    *(float2*)&dstp[(((size_t)bq*HH + h)*NN + ntok)*DK + d] =
                        make_float2(v0 + b2.x, v1 + b2.y);
                } else if (MODE == 1) {
                    *(float2*)&Cout[(size_t)row*DMODEL + col] =
                        make_float2(v0 + b2.x, v1 + b2.y);
                } else {
                    float* p = g_s + (size_t)z*NN*NN + (size_t)row*NN + col;
                    float2 o = *(float2*)p;
                    o.x += 0.125f * v0;
                    o.y += 0.125f * v1;
                    *(float2*)p = o;
                }
            }
        }
    }
}

// ============================================================
// PV: O1 = P @ V, CTA 128(q) x 64(d), K=512, 8 warps of 32x32
// ============================================================
__global__ void __launch_bounds__(256, 2) pv_tc() {
    constexpr int NKT = NN / 8;   // 64
    __shared__ float Ps[4][128][SST];
    __shared__ float Vs[4][8][72];

    int t = threadIdx.x;
    int bh = blockIdx.z, q0 = blockIdx.x * 128;
    const float* P = g_s + ((size_t)bh*NN + q0)*NN;
    const float* V = g_v + (size_t)bh*NN*DK;

    int prow = t >> 1, pc = (t & 1)*4;
    const float* Pp = P + (size_t)prow*NN + pc;
    unsigned sp = (unsigned)__cvta_generic_to_shared(&Ps[0][prow][pc]);
    constexpr unsigned PSTB = 128u*SST*4u;
    int vrow = (t >> 4) & 7, vc = (t & 15)*4;
    const float* Vp = V + (size_t)vrow*DK + vc;
    unsigned sv = (unsigned)__cvta_generic_to_shared(&Vs[0][vrow][vc]);
    constexpr unsigned VSTB = 8u*72u*4u;
    bool vthr = (t < 128);

    int w = t >> 5, l = t & 31;
    int wm = w & 3, wn = w >> 2;
    int r0  = wm*32 + (l >> 2), c0 = l & 3;
    int bn0 = wn*32 + (l >> 2);

    float acc[2][4][4];
    #pragma unroll
    for (int i = 0; i < 2; i++)
        #pragma unroll
        for (int j = 0; j < 4; j++)
            #pragma unroll
            for (int k = 0; k < 4; k++) acc[i][j][k] = 0.0f;

    #pragma unroll
    for (int p = 0; p < 3; p++) {
        cpa16(sp + p*PSTB, Pp + p*8);
        if (vthr) cpa16(sv + p*VSTB, Vp + (size_t)p*8*DK);
        cp_commit();
    }

    for (int kt = 0; kt < NKT; kt++) {
        cp_wait2();
        __syncthreads();
        if (kt + 3 < NKT) {
            int s = (kt + 3) & 3;
            cpa16(sp + s*PSTB, Pp + (kt+3)*8);
            if (vthr) cpa16(sv + s*VSTB, Vp + (size_t)(kt+3)*8*DK);
        }
        cp_commit();

        int s = kt & 3;
        unsigned a[2][4];
        #pragma unroll
        for (int mf = 0; mf < 2; mf++) {
            a[mf][0] = f2tf(Ps[s][r0 + mf*16    ][c0]);
            a[mf][1] = f2tf(Ps[s][r0 + mf*16 + 8][c0]);
            a[mf][2] = f2tf(Ps[s][r0 + mf*16    ][c0+4]);
            a[mf][3] = f2tf(Ps[s][r0 + mf*16 + 8][c0+4]);
        }
        #pragma unroll
        for (int nf = 0; nf < 4; nf++) {
            unsigned b[2];
            b[0] = f2tf(Vs[s][c0  ][bn0 + nf*8]);
            b[1] = f2tf(Vs[s][c0+4][bn0 + nf*8]);
            #pragma unroll
            for (int mf = 0; mf < 2; mf++) mma8(acc[mf][nf], a[mf], b);
        }
    }

    int b = bh >> 4, h = bh & 15;
    #pragma unroll
    for (int mf = 0; mf < 2; mf++) {
        #pragma unroll
        for (int nf = 0; nf < 4; nf++) {
            int col = wn*32 + nf*8 + 2*(l & 3);
            #pragma unroll
            for (int rr = 0; rr < 2; rr++) {
                int row = q0 + wm*32 + mf*16 + rr*8 + (l >> 2);
                *(float2*)&g_o1[((size_t)b*NN + row)*DMODEL + h*DK + col] =
                    make_float2(acc[mf][nf][rr*2 + 0], acc[mf][nf][rr*2 + 1]);
            }
        }
    }
}

// ============================================================
// softmax over k (512), warp per row, in-place
// ============================================================
__global__ void __launch_bounds__(256) softmax_kernel() {
    int row  = blockIdx.x * 8 + (threadIdx.x >> 5);
    int lane = threadIdx.x & 31;
    float* p = g_s + (size_t)row * NN;
    float v[16];
    #pragma unroll
    for (int i = 0; i < 16; i++) v[i] = p[lane + i*32];
    float mx = v[0];
    #pragma unroll
    for (int i = 1; i < 16; i++) mx = fmaxf(mx, v[i]);
    #pragma unroll
    for (int o = 16; o; o >>= 1) mx = fmaxf(mx, __shfl_xor_sync(0xffffffffu, mx, o));
    float sum = 0.0f;
    #pragma unroll
    for (int i = 0; i < 16; i++) { v[i] = __expf(v[i] - mx); sum += v[i]; }
    #pragma unroll
    for (int o = 16; o; o >>= 1) sum += __shfl_xor_sync(0xffffffffu, sum, o);
    float inv = 1.0f / sum;
    #pragma unroll
    for (int i = 0; i < 16; i++) p[lane + i*32] = v[i] * inv;
}

// ============================================================
extern "C" void kernel_launch(void* const* d_in, const int* in_sizes, int n_in,
                              void* d_out, int out_size) {
    const float* queries = (const float*)d_in[0];
    const float* keys    = (const float*)d_in[1];
    const float* values  = (const float*)d_in[2];
    const float* boxes   = (const float*)d_in[3];
    const float* Wq = (const float*)d_in[4];
    const float* bq = (const float*)d_in[5];
    const float* Wk = (const float*)d_in[6];
    const float* bk = (const float*)d_in[7];
    const float* Wv = (const float*)d_in[8];
    const float* bv = (const float*)d_in[9];
    const float* Wo = (const float*)d_in[10];
    const float* bo = (const float*)d_in[11];
    const float* Wg = (const float*)d_in[12];
    const float* bg = (const float*)d_in[13];
    float* out = (float*)d_out;

    boxfeat_kernel<<<16, 256>>>(boxes);
    geom_kernel<<<dim3(32, 32, 8), 256>>>(Wg, bg);
    gemm_tc<0><<<dim3(8, 32, 3), 256>>>(queries, keys, values,
                                        Wq, Wk, Wv, bq, bk, bv, nullptr);
    gemm_tc<2><<<dim3(4, 4, 128), 256>>>(nullptr, nullptr, nullptr,
                                         nullptr, nullptr, nullptr,
                                         nullptr, nullptr, nullptr, nullptr);
    softmax_kernel<<<8192, 256>>>();
    pv_tc<<<dim3(4, 1, 128), 256>>>();
    gemm_tc<1><<<dim3(8, 32, 1), 256>>>(nullptr, nullptr, nullptr,   // A resolved in device code
                                        Wo, nullptr, nullptr,
                                        bo, nullptr, nullptr, out);
}

// round 7
// speedup vs baseline: 1.9611x; 1.1039x over previous
#include <cuda_runtime.h>
#include <math.h>

#define BB 8
#define NN 512
#define DMODEL 1024
#define HH 16
#define DK 64
#define SST 12

// ---- static scratch ----
__device__ float g_q[BB*HH*NN*DK];
__device__ float g_k[BB*HH*NN*DK];
__device__ float g_v[BB*HH*NN*DK];
__device__ float g_s[BB*HH*NN*NN];     // geometry bias (log g), read-only after geom
__device__ float g_o1[BB*NN*DMODEL];
__device__ float g_boxf[BB*NN*6];

// ---- helpers ----
__device__ __forceinline__ unsigned f2tf(float f) {
    unsigned u; asm("cvt.rna.tf32.f32 %0, %1;" : "=r"(u) : "f"(f)); return u;
}
__device__ __forceinline__ void mma8(float* c, const unsigned* a, const unsigned* b) {
    asm volatile("mma.sync.aligned.m16n8k8.row.col.f32.tf32.tf32.f32 "
        "{%0,%1,%2,%3},{%4,%5,%6,%7},{%8,%9},{%0,%1,%2,%3};"
        : "+f"(c[0]), "+f"(c[1]), "+f"(c[2]), "+f"(c[3])
        : "r"(a[0]), "r"(a[1]), "r"(a[2]), "r"(a[3]), "r"(b[0]), "r"(b[1]));
}
__device__ __forceinline__ void cpa16(unsigned dst, const void* src) {
    asm volatile("cp.async.cg.shared.global [%0], [%1], 16;" :: "r"(dst), "l"(src));
}
__device__ __forceinline__ void cp_commit() {
    asm volatile("cp.async.commit_group;" ::: "memory");
}
__device__ __forceinline__ void cp_wait2() {
    asm volatile("cp.async.wait_group 2;" ::: "memory");
}
__device__ __forceinline__ void cp_wait0() {
    asm volatile("cp.async.wait_group 0;" ::: "memory");
}
__device__ __forceinline__ unsigned smaddr(const void* p) {
    return (unsigned)__cvta_generic_to_shared(p);
}
__device__ __forceinline__ unsigned long long pack2(float x, float y) {
    unsigned long long r; asm("mov.b64 %0,{%1,%2};" : "=l"(r) : "f"(x), "f"(y)); return r;
}
__device__ __forceinline__ void unpack2(unsigned long long v, float& x, float& y) {
    asm("mov.b64 {%0,%1},%2;" : "=f"(x), "=f"(y) : "l"(v));
}
__device__ __forceinline__ unsigned long long fma2(unsigned long long a, unsigned long long b,
                                                   unsigned long long c) {
    unsigned long long d;
    asm("fma.rn.f32x2 %0,%1,%2,%3;" : "=l"(d) : "l"(a), "l"(b), "l"(c)); return d;
}

// ============================================================
// box features
// ============================================================
__global__ void boxfeat_kernel(const float* __restrict__ boxes) {
    int i = blockIdx.x * blockDim.x + threadIdx.x;
    if (i >= BB*NN) return;
    float4 bx = ((const float4*)boxes)[i];
    float cx = 0.5f * (bx.x + bx.z);
    float cy = 0.5f * (bx.y + bx.w);
    float w  = bx.z - bx.x + 1.0f;
    float h  = bx.w - bx.y + 1.0f;
    float* o = &g_boxf[i*6];
    o[0] = cx; o[1] = cy;
    o[2] = 1.0f / w; o[3] = 1.0f / h;
    o[4] = __logf(w); o[5] = __logf(h);
}

// ============================================================
// geometry bias, packed f32x2 over head pairs
// ============================================================
__global__ void __launch_bounds__(256) geom_kernel(const float* __restrict__ Wg,
                                                   const float* __restrict__ bg) {
    __shared__ unsigned long long WgS2[32][8];
    __shared__ unsigned long long WgC2[32][8];
    __shared__ float qf[16][6];
    __shared__ float kf[16][6];
    __shared__ float bgs[16];
    int tid = threadIdx.x;
    int b  = blockIdx.z;
    int q0 = blockIdx.y * 16, k0 = blockIdx.x * 16;

    {
        int i = tid >> 3, p = tid & 7;
        WgS2[i][p] = pack2(Wg[(2*p)*64 + i],      Wg[(2*p+1)*64 + i]);
        WgC2[i][p] = pack2(Wg[(2*p)*64 + 32 + i], Wg[(2*p+1)*64 + 32 + i]);
    }
    if (tid < 16) {
        bgs[tid] = bg[tid];
        #pragma unroll
        for (int j = 0; j < 6; j++) qf[tid][j] = g_boxf[(b*NN + q0 + tid)*6 + j];
    } else if (tid < 32) {
        int t = tid - 16;
        #pragma unroll
        for (int j = 0; j < 6; j++) kf[t][j] = g_boxf[(b*NN + k0 + t)*6 + j];
    }
    __syncthreads();

    int ty = tid >> 4, tx = tid & 15;
    float pos[4];
    pos[0] = __logf(fmaxf(fabsf(qf[ty][0] - kf[tx][0]) * qf[ty][2], 1e-3f));
    pos[1] = __logf(fmaxf(fabsf(qf[ty][1] - kf[tx][1]) * qf[ty][3], 1e-3f));
    pos[2] = qf[ty][4] - kf[tx][4];
    pos[3] = qf[ty][5] - kf[tx][5];

    unsigned long long acc2[8];
    #pragma unroll
    for (int p = 0; p < 8; p++) acc2[p] = pack2(bgs[2*p], bgs[2*p+1]);

    const float dm[8] = {1.0f, 0.42169650f, 0.17782794f, 0.07498942f,
                         0.03162278f, 0.01333521f, 0.00562341f, 0.00237137f};
    #pragma unroll
    for (int c = 0; c < 4; c++) {
        float p100 = 100.0f * pos[c];
        #pragma unroll
        for (int f = 0; f < 8; f++) {
            float s, co;
            __sincosf(p100 * dm[f], &s, &co);
            unsigned long long s2 = pack2(s, s), c2 = pack2(co, co);
            int idx = c*8 + f;
            #pragma unroll
            for (int p = 0; p < 8; p++) {
                unsigned long long t = fma2(c2, WgC2[idx][p], acc2[p]);
                acc2[p] = fma2(s2, WgS2[idx][p], t);
            }
        }
    }
    int q = q0 + ty, k = k0 + tx;
    #pragma unroll
    for (int p = 0; p < 8; p++) {
        float x, y;
        unpack2(acc2[p], x, y);
        g_s[(((size_t)b*HH + 2*p  )*NN + q)*NN + k] = __logf(fmaxf(x, 1e-6f));
        g_s[(((size_t)b*HH + 2*p+1)*NN + q)*NN + k] = __logf(fmaxf(y, 1e-6f));
    }
}

// ============================================================
// tf32 GEMM core, 128x128 CTA tile, 8 warps of 32x64, cp.async x4
// MODE 0: QKV projections; MODE 1: output projection (A=g_o1 device-resolved)
// ============================================================
template<int MODE>
__global__ void __launch_bounds__(256, 2) gemm_tc(
    const float* __restrict__ A0, const float* __restrict__ A1, const float* __restrict__ A2,
    const float* __restrict__ B0, const float* __restrict__ B1, const float* __restrict__ B2,
    const float* __restrict__ c0p, const float* __restrict__ c1p, const float* __restrict__ c2p,
    float* __restrict__ Cout)
{
    constexpr int KD  = DMODEL;
    constexpr int NKT = KD / 8;
    __shared__ float As[4][128][SST];
    __shared__ float Bs[4][128][SST];

    int t = threadIdx.x;
    int m0 = blockIdx.y * 128, n0 = blockIdx.x * 128;
    int z = blockIdx.z;

    const float *A, *B, *bias;
    if (MODE == 0) {
        A = (z == 0) ? A0 : (z == 1) ? A1 : A2;
        B = (z == 0) ? B0 : (z == 1) ? B1 : B2;
        bias = (z == 0) ? c0p : (z == 1) ? c1p : c2p;
    } else {
        A = g_o1;              // device-side symbol resolution
        B = B0; bias = c0p;
    }

    int lrow = t >> 1, lc = (t & 1) * 4;
    const float* Ap = A + (size_t)(m0 + lrow)*KD + lc;
    const float* Bp = B + (size_t)(n0 + lrow)*KD + lc;
    unsigned sa = smaddr(&As[0][lrow][lc]);
    unsigned sb = smaddr(&Bs[0][lrow][lc]);
    constexpr unsigned STB = 128u * SST * 4u;

    int w = t >> 5, l = t & 31;
    int wm = w & 3, wn = w >> 2;
    int r0  = wm*32 + (l >> 2), c0 = l & 3;
    int bn0 = wn*64 + (l >> 2);

    float acc[2][8][4];
    #pragma unroll
    for (int i = 0; i < 2; i++)
        #pragma unroll
        for (int j = 0; j < 8; j++)
            #pragma unroll
            for (int k = 0; k < 4; k++) acc[i][j][k] = 0.0f;

    #pragma unroll
    for (int p = 0; p < 3; p++) {
        cpa16(sa + (p & 3)*STB, Ap + p*8);
        cpa16(sb + (p & 3)*STB, Bp + p*8);
        cp_commit();
    }

    for (int kt = 0; kt < NKT; kt++) {
        cp_wait2();
        __syncthreads();
        if (kt + 3 < NKT) {
            int s = (kt + 3) & 3;
            cpa16(sa + s*STB, Ap + (kt+3)*8);
            cpa16(sb + s*STB, Bp + (kt+3)*8);
        }
        cp_commit();

        int s = kt & 3;
        unsigned a[2][4];
        #pragma unroll
        for (int mf = 0; mf < 2; mf++) {
            a[mf][0] = f2tf(As[s][r0 + mf*16    ][c0]);
            a[mf][1] = f2tf(As[s][r0 + mf*16 + 8][c0]);
            a[mf][2] = f2tf(As[s][r0 + mf*16    ][c0+4]);
            a[mf][3] = f2tf(As[s][r0 + mf*16 + 8][c0+4]);
        }
        #pragma unroll
        for (int nf = 0; nf < 8; nf++) {
            unsigned b[2];
            b[0] = f2tf(Bs[s][bn0 + nf*8][c0]);
            b[1] = f2tf(Bs[s][bn0 + nf*8][c0+4]);
            #pragma unroll
            for (int mf = 0; mf < 2; mf++) mma8(acc[mf][nf], a[mf], b);
        }
    }

    #pragma unroll
    for (int mf = 0; mf < 2; mf++) {
        #pragma unroll
        for (int nf = 0; nf < 8; nf++) {
            int col = n0 + wn*64 + nf*8 + 2*(l & 3);
            float2 b2 = *(const float2*)(bias + col);
            #pragma unroll
            for (int rr = 0; rr < 2; rr++) {
                int row = m0 + wm*32 + mf*16 + rr*8 + (l >> 2);
                float v0 = acc[mf][nf][rr*2 + 0] + b2.x;
                float v1 = acc[mf][nf][rr*2 + 1] + b2.y;
                if (MODE == 0) {
                    int h = col >> 6, d = col & 63;
                    int bq = row >> 9, ntok = row & (NN-1);
                    float* dstp = (z == 0) ? g_q : (z == 1) ? g_k : g_v;
                    *(float2*)&dstp[(((size_t)bq*HH + h)*NN + ntok)*DK + d] =
                        make_float2(v0, v1);
                } else {
                    *(float2*)&Cout[(size_t)row*DMODEL + col] = make_float2(v0, v1);
                }
            }
        }
    }
}

// ============================================================
// fused attention: S = bias + (Q/8)Kt per k-tile, online softmax, O += P V
// CTA: 128 q-rows x one bh. 8 warps, warp = 16 q-rows x 64 k-cols.
// smem: Ks[2][64][68] | Vs[2][64][72] | Ps[128][68] (Q staged in Ps first)
// ============================================================
#define KS_ST 68
#define VS_ST 72
#define PS_ST 68
#define FUSED_SMEM ((2*64*KS_ST + 2*64*VS_ST + 128*PS_ST) * 4)

__global__ void __launch_bounds__(256, 2) fused_attn() {
    extern __shared__ float sm[];
    float* KsB = sm;                       // [2][64][68]
    float* VsB = sm + 2*64*KS_ST;          // [2][64][72]
    float* Ps  = VsB + 2*64*VS_ST;         // [128][68]

    int t = threadIdx.x;
    int bh = blockIdx.y;
    int q0 = blockIdx.x * 128;
    const float* Qg = g_q + ((size_t)bh*NN + q0)*DK;
    const float* Kg = g_k + (size_t)bh*NN*DK;
    const float* Vg = g_v + (size_t)bh*NN*DK;
    const float* Sg = g_s + (size_t)bh*NN*NN;

    int w = t >> 5, l = t & 31;
    int r0 = l >> 2, c0 = l & 3;
    int qrow = w*16 + r0;                  // warp-owned rows qrow, qrow+8

    // ---- prologue: stage Q into Ps, load K/V tile 0 ----
    {
        int row = t >> 1, col = (t & 1) * 32;   // 2 float4 per half: use 8x loop below
    }
    #pragma unroll
    for (int i = 0; i < 8; i++) {
        int idx = t + i*256;
        int row = idx >> 4, col = (idx & 15) * 4;
        cpa16(smaddr(Ps + row*PS_ST + col), Qg + row*DK + col);
    }
    #pragma unroll
    for (int i = 0; i < 4; i++) {
        int idx = t + i*256;
        int row = idx >> 4, col = (idx & 15) * 4;
        cpa16(smaddr(KsB + row*KS_ST + col), Kg + row*DK + col);
        cpa16(smaddr(VsB + row*VS_ST + col), Vg + row*DK + col);
    }
    cp_commit();
    cp_wait0();
    __syncthreads();

    // ---- Q fragments (scaled by 1/8, tf32) ----
    unsigned qa[8][4];
    #pragma unroll
    for (int kc = 0; kc < 8; kc++) {
        qa[kc][0] = f2tf(0.125f * Ps[qrow*PS_ST     + kc*8 + c0]);
        qa[kc][1] = f2tf(0.125f * Ps[(qrow+8)*PS_ST + kc*8 + c0]);
        qa[kc][2] = f2tf(0.125f * Ps[qrow*PS_ST     + kc*8 + c0 + 4]);
        qa[kc][3] = f2tf(0.125f * Ps[(qrow+8)*PS_ST + kc*8 + c0 + 4]);
    }

    float Oa[8][4];
    #pragma unroll
    for (int nf = 0; nf < 8; nf++)
        #pragma unroll
        for (int k = 0; k < 4; k++) Oa[nf][k] = 0.0f;
    float m0v = -INFINITY, m1v = -INFINITY, l0v = 0.0f, l1v = 0.0f;

    const int NT = NN / 64;   // 8 k-tiles
    for (int j = 0; j < NT; j++) {
        if (j > 0) cp_wait0();
        __syncthreads();                       // tile j visible; tile j-1 consumers done
        if (j + 1 < NT) {
            int nb = (j + 1) & 1;
            float* Ksn = KsB + nb*64*KS_ST;
            float* Vsn = VsB + nb*64*VS_ST;
            #pragma unroll
            for (int i = 0; i < 4; i++) {
                int idx = t + i*256;
                int row = idx >> 4, col = (idx & 15) * 4;
                cpa16(smaddr(Ksn + row*KS_ST + col), Kg + ((j+1)*64 + row)*DK + col);
                cpa16(smaddr(Vsn + row*VS_ST + col), Vg + ((j+1)*64 + row)*DK + col);
            }
        }
        cp_commit();

        const float* Ks = KsB + (j & 1)*64*KS_ST;
        const float* Vs = VsB + (j & 1)*64*VS_ST;

        // S acc init = bias tile from g_s
        float acc[8][4];
        {
            const float* br0 = Sg + (size_t)(q0 + qrow)*NN + j*64;
            const float* br1 = br0 + 8*NN;
            #pragma unroll
            for (int nf = 0; nf < 8; nf++) {
                float2 t0 = *(const float2*)(br0 + nf*8 + 2*c0);
                float2 t1 = *(const float2*)(br1 + nf*8 + 2*c0);
                acc[nf][0] = t0.x; acc[nf][1] = t0.y;
                acc[nf][2] = t1.x; acc[nf][3] = t1.y;
            }
        }
        // S += Q' K^T
        #pragma unroll
        for (int kc = 0; kc < 8; kc++) {
            #pragma unroll
            for (int nf = 0; nf < 8; nf++) {
                unsigned b[2];
                b[0] = f2tf(Ks[(r0 + nf*8)*KS_ST + kc*8 + c0]);
                b[1] = f2tf(Ks[(r0 + nf*8)*KS_ST + kc*8 + c0 + 4]);
                mma8(acc[nf], qa[kc], b);
            }
        }

        // online softmax update
        float mx0 = -INFINITY, mx1 = -INFINITY;
        #pragma unroll
        for (int nf = 0; nf < 8; nf++) {
            mx0 = fmaxf(mx0, fmaxf(acc[nf][0], acc[nf][1]));
            mx1 = fmaxf(mx1, fmaxf(acc[nf][2], acc[nf][3]));
        }
        #pragma unroll
        for (int o = 1; o <= 2; o <<= 1) {
            mx0 = fmaxf(mx0, __shfl_xor_sync(0xffffffffu, mx0, o));
            mx1 = fmaxf(mx1, __shfl_xor_sync(0xffffffffu, mx1, o));
        }
        float mn0 = fmaxf(m0v, mx0), mn1 = fmaxf(m1v, mx1);
        float sc0 = __expf(m0v - mn0), sc1 = __expf(m1v - mn1);
        m0v = mn0; m1v = mn1;
        float s0 = 0.0f, s1 = 0.0f;
        #pragma unroll
        for (int nf = 0; nf < 8; nf++) {
            acc[nf][0] = __expf(acc[nf][0] - mn0);
            acc[nf][1] = __expf(acc[nf][1] - mn0);
            acc[nf][2] = __expf(acc[nf][2] - mn1);
            acc[nf][3] = __expf(acc[nf][3] - mn1);
            s0 += acc[nf][0] + acc[nf][1];
            s1 += acc[nf][2] + acc[nf][3];
        }
        #pragma unroll
        for (int o = 1; o <= 2; o <<= 1) {
            s0 += __shfl_xor_sync(0xffffffffu, s0, o);
            s1 += __shfl_xor_sync(0xffffffffu, s1, o);
        }
        l0v = l0v * sc0 + s0;
        l1v = l1v * sc1 + s1;
        #pragma unroll
        for (int nf = 0; nf < 8; nf++) {
            Oa[nf][0] *= sc0; Oa[nf][1] *= sc0;
            Oa[nf][2] *= sc1; Oa[nf][3] *= sc1;
        }

        // P -> smem (warp-own rows), then PV
        #pragma unroll
        for (int nf = 0; nf < 8; nf++) {
            *(float2*)&Ps[qrow*PS_ST     + nf*8 + 2*c0] = make_float2(acc[nf][0], acc[nf][1]);
            *(float2*)&Ps[(qrow+8)*PS_ST + nf*8 + 2*c0] = make_float2(acc[nf][2], acc[nf][3]);
        }
        __syncwarp();
        #pragma unroll
        for (int kc = 0; kc < 8; kc++) {
            unsigned a[4];
            a[0] = f2tf(Ps[qrow*PS_ST     + kc*8 + c0]);
            a[1] = f2tf(Ps[(qrow+8)*PS_ST + kc*8 + c0]);
            a[2] = f2tf(Ps[qrow*PS_ST     + kc*8 + c0 + 4]);
            a[3] = f2tf(Ps[(qrow+8)*PS_ST + kc*8 + c0 + 4]);
            #pragma unroll
            for (int nf = 0; nf < 8; nf++) {
                unsigned b[2];
                b[0] = f2tf(Vs[(kc*8 + c0    )*VS_ST + r0 + nf*8]);
                b[1] = f2tf(Vs[(kc*8 + c0 + 4)*VS_ST + r0 + nf*8]);
                mma8(Oa[nf], a, b);
            }
        }
        __syncwarp();
    }

    // epilogue: O /= l, write to g_o1
    float inv0 = 1.0f / l0v, inv1 = 1.0f / l1v;
    int b = bh >> 4, h = bh & 15;
    float* O0 = g_o1 + ((size_t)b*NN + q0 + qrow)*DMODEL + h*DK;
    float* O1 = O0 + 8*DMODEL;
    #pragma unroll
    for (int nf = 0; nf < 8; nf++) {
        *(float2*)(O0 + nf*8 + 2*c0) = make_float2(Oa[nf][0]*inv0, Oa[nf][1]*inv0);
        *(float2*)(O1 + nf*8 + 2*c0) = make_float2(Oa[nf][2]*inv1, Oa[nf][3]*inv1);
    }
}

// ============================================================
extern "C" void kernel_launch(void* const* d_in, const int* in_sizes, int n_in,
                              void* d_out, int out_size) {
    const float* queries = (const float*)d_in[0];
    const float* keys    = (const float*)d_in[1];
    const float* values  = (const float*)d_in[2];
    const float* boxes   = (const float*)d_in[3];
    const float* Wq = (const float*)d_in[4];
    const float* bq = (const float*)d_in[5];
    const float* Wk = (const float*)d_in[6];
    const float* bk = (const float*)d_in[7];
    const float* Wv = (const float*)d_in[8];
    const float* bv = (const float*)d_in[9];
    const float* Wo = (const float*)d_in[10];
    const float* bo = (const float*)d_in[11];
    const float* Wg = (const float*)d_in[12];
    const float* bg = (const float*)d_in[13];
    float* out = (float*)d_out;

    cudaFuncSetAttribute(fused_attn, cudaFuncAttributeMaxDynamicSharedMemorySize,
                         FUSED_SMEM);

    boxfeat_kernel<<<16, 256>>>(boxes);
    geom_kernel<<<dim3(32, 32, 8), 256>>>(Wg, bg);
    gemm_tc<0><<<dim3(8, 32, 3), 256>>>(queries, keys, values,
                                        Wq, Wk, Wv, bq, bk, bv, nullptr);
    fused_attn<<<dim3(4, 128), 256, FUSED_SMEM>>>();
    gemm_tc<1><<<dim3(8, 32, 1), 256>>>(nullptr, nullptr, nullptr,
                                        Wo, nullptr, nullptr,
                                        bo, nullptr, nullptr, out);
}

// round 10
// speedup vs baseline: 2.2361x; 1.1402x over previous
#include <cuda_runtime.h>
#include <math.h>

#define BB 8
#define NN 512
#define DMODEL 1024
#define HH 16
#define DK 64
#define SST 12

// ---- static scratch ----
__device__ float g_q[BB*HH*NN*DK];        // tf32-pre-rounded after projection
__device__ float g_k[BB*HH*NN*DK];
__device__ float g_v[BB*HH*NN*DK];
__device__ float g_s[BB*HH*NN*NN];        // geometry bias (log g), fp32
__device__ float g_o1[BB*NN*DMODEL];      // attn output, tf32-pre-rounded
__device__ float g_boxf[BB*NN*6];
__device__ float g_act[3*BB*NN*DMODEL];   // tf32-rounded activations
__device__ float g_wr[4*DMODEL*DMODEL];   // tf32-rounded weights Wq,Wk,Wv,Wo

// ---- helpers ----
__device__ __forceinline__ unsigned f2tf(float f) {
    unsigned u; asm("cvt.rna.tf32.f32 %0, %1;" : "=r"(u) : "f"(f)); return u;
}
__device__ __forceinline__ float r2(float f) { return __uint_as_float(f2tf(f)); }
__device__ __forceinline__ void mma8(float* c, const unsigned* a, const unsigned* b) {
    asm volatile("mma.sync.aligned.m16n8k8.row.col.f32.tf32.tf32.f32 "
        "{%0,%1,%2,%3},{%4,%5,%6,%7},{%8,%9},{%0,%1,%2,%3};"
        : "+f"(c[0]), "+f"(c[1]), "+f"(c[2]), "+f"(c[3])
        : "r"(a[0]), "r"(a[1]), "r"(a[2]), "r"(a[3]), "r"(b[0]), "r"(b[1]));
}
__device__ __forceinline__ void ldsm4(unsigned& r0, unsigned& r1, unsigned& r2v,
                                      unsigned& r3, unsigned a) {
    asm volatile("ldmatrix.sync.aligned.m8n8.x4.shared.b16 {%0,%1,%2,%3}, [%4];"
        : "=r"(r0), "=r"(r1), "=r"(r2v), "=r"(r3) : "r"(a));
}
__device__ __forceinline__ void cpa16(unsigned dst, const void* src) {
    asm volatile("cp.async.cg.shared.global [%0], [%1], 16;" :: "r"(dst), "l"(src));
}
__device__ __forceinline__ void cp_commit() {
    asm volatile("cp.async.commit_group;" ::: "memory");
}
__device__ __forceinline__ void cp_wait2() {
    asm volatile("cp.async.wait_group 2;" ::: "memory");
}
__device__ __forceinline__ void cp_wait0() {
    asm volatile("cp.async.wait_group 0;" ::: "memory");
}
__device__ __forceinline__ unsigned smaddr(const void* p) {
    return (unsigned)__cvta_generic_to_shared(p);
}
__device__ __forceinline__ unsigned long long pack2(float x, float y) {
    unsigned long long r; asm("mov.b64 %0,{%1,%2};" : "=l"(r) : "f"(x), "f"(y)); return r;
}
__device__ __forceinline__ void unpack2(unsigned long long v, float& x, float& y) {
    asm("mov.b64 {%0,%1},%2;" : "=f"(x), "=f"(y) : "l"(v));
}
__device__ __forceinline__ unsigned long long fma2(unsigned long long a, unsigned long long b,
                                                   unsigned long long c) {
    unsigned long long d;
    asm("fma.rn.f32x2 %0,%1,%2,%3;" : "=l"(d) : "l"(a), "l"(b), "l"(c)); return d;
}

// ============================================================
// box features
// ============================================================
__global__ void boxfeat_kernel(const float* __restrict__ boxes) {
    int i = blockIdx.x * blockDim.x + threadIdx.x;
    if (i >= BB*NN) return;
    float4 bx = ((const float4*)boxes)[i];
    float cx = 0.5f * (bx.x + bx.z);
    float cy = 0.5f * (bx.y + bx.w);
    float w  = bx.z - bx.x + 1.0f;
    float h  = bx.w - bx.y + 1.0f;
    float* o = &g_boxf[i*6];
    o[0] = cx; o[1] = cy;
    o[2] = 1.0f / w; o[3] = 1.0f / h;
    o[4] = __logf(w); o[5] = __logf(h);
}

// ============================================================
// pre-round activations + weights to tf32 (rna)
// ============================================================
__global__ void prep_kernel(const float* __restrict__ q, const float* __restrict__ k,
                            const float* __restrict__ v, const float* __restrict__ wq,
                            const float* __restrict__ wk, const float* __restrict__ wv,
                            const float* __restrict__ wo) {
    int z = blockIdx.y;
    const float* src = (z==0)?q:(z==1)?k:(z==2)?v:(z==3)?wq:(z==4)?wk:(z==5)?wv:wo;
    float* dst = (z < 3) ? g_act + (size_t)z*(BB*NN*DMODEL)
                         : g_wr + (size_t)(z-3)*(DMODEL*DMODEL);
    int n4 = (z < 3) ? (BB*NN*DMODEL/4) : (DMODEL*DMODEL/4);
    int i = blockIdx.x*256 + threadIdx.x;
    if (i < n4) {
        float4 a = ((const float4*)src)[i];
        ((uint4*)dst)[i] = make_uint4(f2tf(a.x), f2tf(a.y), f2tf(a.z), f2tf(a.w));
    }
}

// ============================================================
// geometry bias, packed f32x2 over head pairs
// ============================================================
__global__ void __launch_bounds__(256) geom_kernel(const float* __restrict__ Wg,
                                                   const float* __restrict__ bg) {
    __shared__ unsigned long long WgS2[32][8];
    __shared__ unsigned long long WgC2[32][8];
    __shared__ float qf[16][6];
    __shared__ float kf[16][6];
    __shared__ float bgs[16];
    int tid = threadIdx.x;
    int b  = blockIdx.z;
    int q0 = blockIdx.y * 16, k0 = blockIdx.x * 16;

    {
        int i = tid >> 3, p = tid & 7;
        WgS2[i][p] = pack2(Wg[(2*p)*64 + i],      Wg[(2*p+1)*64 + i]);
        WgC2[i][p] = pack2(Wg[(2*p)*64 + 32 + i], Wg[(2*p+1)*64 + 32 + i]);
    }
    if (tid < 16) {
        bgs[tid] = bg[tid];
        #pragma unroll
        for (int j = 0; j < 6; j++) qf[tid][j] = g_boxf[(b*NN + q0 + tid)*6 + j];
    } else if (tid < 32) {
        int t = tid - 16;
        #pragma unroll
        for (int j = 0; j < 6; j++) kf[t][j] = g_boxf[(b*NN + k0 + t)*6 + j];
    }
    __syncthreads();

    int ty = tid >> 4, tx = tid & 15;
    float pos[4];
    pos[0] = __logf(fmaxf(fabsf(qf[ty][0] - kf[tx][0]) * qf[ty][2], 1e-3f));
    pos[1] = __logf(fmaxf(fabsf(qf[ty][1] - kf[tx][1]) * qf[ty][3], 1e-3f));
    pos[2] = qf[ty][4] - kf[tx][4];
    pos[3] = qf[ty][5] - kf[tx][5];

    unsigned long long acc2[8];
    #pragma unroll
    for (int p = 0; p < 8; p++) acc2[p] = pack2(bgs[2*p], bgs[2*p+1]);

    const float dm[8] = {1.0f, 0.42169650f, 0.17782794f, 0.07498942f,
                         0.03162278f, 0.01333521f, 0.00562341f, 0.00237137f};
    #pragma unroll
    for (int c = 0; c < 4; c++) {
        float p100 = 100.0f * pos[c];
        #pragma unroll
        for (int f = 0; f < 8; f++) {
            float s, co;
            __sincosf(p100 * dm[f], &s, &co);
            unsigned long long s2 = pack2(s, s), c2 = pack2(co, co);
            int idx = c*8 + f;
            #pragma unroll
            for (int p = 0; p < 8; p++) {
                unsigned long long t = fma2(c2, WgC2[idx][p], acc2[p]);
                acc2[p] = fma2(s2, WgS2[idx][p], t);
            }
        }
    }
    int q = q0 + ty, k = k0 + tx;
    #pragma unroll
    for (int p = 0; p < 8; p++) {
        float x, y;
        unpack2(acc2[p], x, y);
        g_s[(((size_t)b*HH + 2*p  )*NN + q)*NN + k] = __logf(fmaxf(x, 1e-6f));
        g_s[(((size_t)b*HH + 2*p+1)*NN + q)*NN + k] = __logf(fmaxf(y, 1e-6f));
    }
}

// ============================================================
// tf32 GEMM, 128x128 CTA tile, 8 warps of 32x64, cp.async x4,
// LDSM fragments, no in-loop CVT (inputs pre-rounded).
// MODE 0: QKV (A=g_act[z], B=g_wr[z], rounded scatter to g_q/g_k/g_v)
// MODE 1: O-proj (A=g_o1, B=g_wr[3], dst=Cout, unrounded)
// ============================================================
template<int MODE>
__global__ void __launch_bounds__(256, 2) gemm_tc(
    const float* __restrict__ b0p, const float* __restrict__ b1p,
    const float* __restrict__ b2p, float* __restrict__ Cout)
{
    constexpr int KD  = DMODEL;
    constexpr int NKT = KD / 8;
    __shared__ float As[4][128][SST];
    __shared__ float Bs[4][128][SST];

    int t = threadIdx.x;
    int m0 = blockIdx.y * 128, n0 = blockIdx.x * 128;
    int z = blockIdx.z;

    const float *A, *B, *bias;
    if (MODE == 0) {
        A = g_act + (size_t)z*(BB*NN*DMODEL);
        B = g_wr  + (size_t)z*(DMODEL*DMODEL);
        bias = (z == 0) ? b0p : (z == 1) ? b1p : b2p;
    } else {
        A = g_o1;
        B = g_wr + 3*(size_t)(DMODEL*DMODEL);
        bias = b0p;
    }

    int lrow = t >> 1, lc = (t & 1) * 4;
    const float* Ap = A + (size_t)(m0 + lrow)*KD + lc;
    const float* Bp = B + (size_t)(n0 + lrow)*KD + lc;
    unsigned sa = smaddr(&As[0][lrow][lc]);
    unsigned sb = smaddr(&Bs[0][lrow][lc]);
    constexpr unsigned STB = 128u * SST * 4u;

    int w = t >> 5, l = t & 31;
    int wm = w & 3, wn = w >> 2;
    // ldmatrix per-lane address components
    int lj   = l & 7;
    int aRow = ((l >> 3) & 1) * 8 + lj;
    int aCol = (l >> 4) * 4;
    int bRow = (l >> 4) * 8 + lj;
    int bCol = ((l >> 3) & 1) * 4;

    float acc[2][8][4];
    #pragma unroll
    for (int i = 0; i < 2; i++)
        #pragma unroll
        for (int j = 0; j < 8; j++)
            #pragma unroll
            for (int k = 0; k < 4; k++) acc[i][j][k] = 0.0f;

    #pragma unroll
    for (int p = 0; p < 3; p++) {
        cpa16(sa + p*STB, Ap + p*8);
        cpa16(sb + p*STB, Bp + p*8);
        cp_commit();
    }

    for (int kt = 0; kt < NKT; kt++) {
        cp_wait2();
        __syncthreads();
        if (kt + 3 < NKT) {
            int s = (kt + 3) & 3;
            cpa16(sa + s*STB, Ap + (kt+3)*8);
            cpa16(sb + s*STB, Bp + (kt+3)*8);
        }
        cp_commit();

        int s = kt & 3;
        unsigned a[2][4];
        ldsm4(a[0][0], a[0][1], a[0][2], a[0][3],
              smaddr(&As[s][wm*32 + aRow][aCol]));
        ldsm4(a[1][0], a[1][1], a[1][2], a[1][3],
              smaddr(&As[s][wm*32 + 16 + aRow][aCol]));
        #pragma unroll
        for (int p = 0; p < 4; p++) {
            unsigned bb[4];
            ldsm4(bb[0], bb[1], bb[2], bb[3],
                  smaddr(&Bs[s][wn*64 + p*16 + bRow][bCol]));
            mma8(acc[0][2*p],   a[0], bb);
            mma8(acc[0][2*p+1], a[0], bb + 2);
            mma8(acc[1][2*p],   a[1], bb);
            mma8(acc[1][2*p+1], a[1], bb + 2);
        }
    }

    // epilogue
    #pragma unroll
    for (int mf = 0; mf < 2; mf++) {
        #pragma unroll
        for (int nf = 0; nf < 8; nf++) {
            int col = n0 + wn*64 + nf*8 + 2*(l & 3);
            float2 b2 = *(const float2*)(bias + col);
            #pragma unroll
            for (int rr = 0; rr < 2; rr++) {
                int row = m0 + wm*32 + mf*16 + rr*8 + (l >> 2);
                float v0 = acc[mf][nf][rr*2 + 0] + b2.x;
                float v1 = acc[mf][nf][rr*2 + 1] + b2.y;
                if (MODE == 0) {
                    int h = col >> 6, d = col & 63;
                    int bq = row >> 9, ntok = row & (NN-1);
                    float* dstp = (z == 0) ? g_q : (z == 1) ? g_k : g_v;
                    *(float2*)&dstp[(((size_t)bq*HH + h)*NN + ntok)*DK + d] =
                        make_float2(r2(v0), r2(v1));
                } else {
                    *(float2*)&Cout[(size_t)row*DMODEL + col] = make_float2(v0, v1);
                }
            }
        }
    }
}

// ============================================================
// fused attention: S = bias + (Q/8)Kt, online softmax, O += P V
// Q/K/V pre-rounded tf32 -> no CVT; LDSM for K (b) and P (a) fragments.
// ============================================================
#define KS_ST 68
#define VS_ST 72
#define PS_ST 68
#define FUSED_SMEM ((2*64*KS_ST + 2*64*VS_ST + 128*PS_ST) * 4)

__global__ void __launch_bounds__(256, 2) fused_attn() {
    extern __shared__ float smf[];
    float* KsB = smf;
    float* VsB = smf + 2*64*KS_ST;
    float* Ps  = VsB + 2*64*VS_ST;

    int t = threadIdx.x;
    int bh = blockIdx.y;
    int q0 = blockIdx.x * 128;
    const float* Qg = g_q + ((size_t)bh*NN + q0)*DK;
    const float* Kg = g_k + (size_t)bh*NN*DK;
    const float* Vg = g_v + (size_t)bh*NN*DK;
    const float* Sg = g_s + (size_t)bh*NN*NN;

    int w = t >> 5, l = t & 31;
    int r0 = l >> 2, c0 = l & 3;
    int qrow = w*16 + r0;
    int lj   = l & 7;
    int aRow = ((l >> 3) & 1) * 8 + lj;
    int aCol = (l >> 4) * 4;
    int bRow = (l >> 4) * 8 + lj;
    int bCol = ((l >> 3) & 1) * 4;

    #pragma unroll
    for (int i = 0; i < 8; i++) {
        int idx = t + i*256;
        int row = idx >> 4, col = (idx & 15) * 4;
        cpa16(smaddr(Ps + row*PS_ST + col), Qg + row*DK + col);
    }
    #pragma unroll
    for (int i = 0; i < 4; i++) {
        int idx = t + i*256;
        int row = idx >> 4, col = (idx & 15) * 4;
        cpa16(smaddr(KsB + row*KS_ST + col), Kg + row*DK + col);
        cpa16(smaddr(VsB + row*VS_ST + col), Vg + row*DK + col);
    }
    cp_commit();
    cp_wait0();
    __syncthreads();

    // Q fragments: pre-rounded; *0.125 is exact (power of 2) -> still tf32
    unsigned qa[8][4];
    #pragma unroll
    for (int kc = 0; kc < 8; kc++) {
        qa[kc][0] = __float_as_uint(0.125f * Ps[qrow*PS_ST     + kc*8 + c0]);
        qa[kc][1] = __float_as_uint(0.125f * Ps[(qrow+8)*PS_ST + kc*8 + c0]);
        qa[kc][2] = __float_as_uint(0.125f * Ps[qrow*PS_ST     + kc*8 + c0 + 4]);
        qa[kc][3] = __float_as_uint(0.125f * Ps[(qrow+8)*PS_ST + kc*8 + c0 + 4]);
    }

    float Oa[8][4];
    #pragma unroll
    for (int nf = 0; nf < 8; nf++)
        #pragma unroll
        for (int k = 0; k < 4; k++) Oa[nf][k] = 0.0f;
    float m0v = -INFINITY, m1v = -INFINITY, l0v = 0.0f, l1v = 0.0f;

    const int NT = NN / 64;
    for (int j = 0; j < NT; j++) {
        if (j > 0) cp_wait0();
        __syncthreads();
        if (j + 1 < NT) {
            int nb = (j + 1) & 1;
            float* Ksn = KsB + nb*64*KS_ST;
            float* Vsn = VsB + nb*64*VS_ST;
            #pragma unroll
            for (int i = 0; i < 4; i++) {
                int idx = t + i*256;
                int row = idx >> 4, col = (idx & 15) * 4;
                cpa16(smaddr(Ksn + row*KS_ST + col), Kg + ((j+1)*64 + row)*DK + col);
                cpa16(smaddr(Vsn + row*VS_ST + col), Vg + ((j+1)*64 + row)*DK + col);
            }
        }
        cp_commit();

        const float* Ks = KsB + (j & 1)*64*KS_ST;
        const float* Vs = VsB + (j & 1)*64*VS_ST;

        // S acc init = bias tile
        float acc[8][4];
        {
            const float* br0 = Sg + (size_t)(q0 + qrow)*NN + j*64;
            const float* br1 = br0 + 8*NN;
            #pragma unroll
            for (int nf = 0; nf < 8; nf++) {
                float2 t0 = *(const float2*)(br0 + nf*8 + 2*c0);
                float2 t1 = *(const float2*)(br1 + nf*8 + 2*c0);
                acc[nf][0] = t0.x; acc[nf][1] = t0.y;
                acc[nf][2] = t1.x; acc[nf][3] = t1.y;
            }
        }
        // S += Q' K^T  (K fragments via LDSM)
        #pragma unroll
        for (int kc = 0; kc < 8; kc++) {
            #pragma unroll
            for (int p = 0; p < 4; p++) {
                unsigned bb[4];
                ldsm4(bb[0], bb[1], bb[2], bb[3],
                      smaddr(&Ks[(p*16 + bRow)*KS_ST + kc*8 + bCol]));
                mma8(acc[2*p],   qa[kc], bb);
                mma8(acc[2*p+1], qa[kc], bb + 2);
            }
        }

        // online softmax
        float mx0 = -INFINITY, mx1 = -INFINITY;
        #pragma unroll
        for (int nf = 0; nf < 8; nf++) {
            mx0 = fmaxf(mx0, fmaxf(acc[nf][0], acc[nf][1]));
            mx1 = fmaxf(mx1, fmaxf(acc[nf][2], acc[nf][3]));
        }
        #pragma unroll
        for (int o = 1; o <= 2; o <<= 1) {
            mx0 = fmaxf(mx0, __shfl_xor_sync(0xffffffffu, mx0, o));
            mx1 = fmaxf(mx1, __shfl_xor_sync(0xffffffffu, mx1, o));
        }
        float mn0 = fmaxf(m0v, mx0), mn1 = fmaxf(m1v, mx1);
        float sc0 = __expf(m0v - mn0), sc1 = __expf(m1v - mn1);
        m0v = mn0; m1v = mn1;
        float s0 = 0.0f, s1 = 0.0f;
        #pragma unroll
        for (int nf = 0; nf < 8; nf++) {
            acc[nf][0] = __expf(acc[nf][0] - mn0);
            acc[nf][1] = __expf(acc[nf][1] - mn0);
            acc[nf][2] = __expf(acc[nf][2] - mn1);
            acc[nf][3] = __expf(acc[nf][3] - mn1);
            s0 += acc[nf][0] + acc[nf][1];
            s1 += acc[nf][2] + acc[nf][3];
        }
        #pragma unroll
        for (int o = 1; o <= 2; o <<= 1) {
            s0 += __shfl_xor_sync(0xffffffffu, s0, o);
            s1 += __shfl_xor_sync(0xffffffffu, s1, o);
        }
        l0v = l0v * sc0 + s0;
        l1v = l1v * sc1 + s1;
        #pragma unroll
        for (int nf = 0; nf < 8; nf++) {
            Oa[nf][0] *= sc0; Oa[nf][1] *= sc0;
            Oa[nf][2] *= sc1; Oa[nf][3] *= sc1;
        }

        // P -> smem (rounded), PV via LDSM (a) + plain V loads (b)
        #pragma unroll
        for (int nf = 0; nf < 8; nf++) {
            *(float2*)&Ps[qrow*PS_ST     + nf*8 + 2*c0] =
                make_float2(r2(acc[nf][0]), r2(acc[nf][1]));
            *(float2*)&Ps[(qrow+8)*PS_ST + nf*8 + 2*c0] =
                make_float2(r2(acc[nf][2]), r2(acc[nf][3]));
        }
        __syncwarp();
        #pragma unroll
        for (int kc = 0; kc < 8; kc++) {
            unsigned a4[4];
            ldsm4(a4[0], a4[1], a4[2], a4[3],
                  smaddr(&Ps[(w*16 + aRow)*PS_ST + kc*8 + aCol]));
            #pragma unroll
            for (int nf = 0; nf < 8; nf++) {
                unsigned b[2];
                b[0] = __float_as_uint(Vs[(kc*8 + c0    )*VS_ST + r0 + nf*8]);
                b[1] = __float_as_uint(Vs[(kc*8 + c0 + 4)*VS_ST + r0 + nf*8]);
                mma8(Oa[nf], a4, b);
            }
        }
        __syncwarp();
    }

    // epilogue: O /= l, round (feeds O-proj), write g_o1
    float inv0 = 1.0f / l0v, inv1 = 1.0f / l1v;
    int b = bh >> 4, h = bh & 15;
    float* O0 = g_o1 + ((size_t)b*NN + q0 + qrow)*DMODEL + h*DK;
    float* O1 = O0 + 8*DMODEL;
    #pragma unroll
    for (int nf = 0; nf < 8; nf++) {
        *(float2*)(O0 + nf*8 + 2*c0) =
            make_float2(r2(Oa[nf][0]*inv0), r2(Oa[nf][1]*inv0));
        *(float2*)(O1 + nf*8 + 2*c0) =
            make_float2(r2(Oa[nf][2]*inv1), r2(Oa[nf][3]*inv1));
    }
}

// ============================================================
extern "C" void kernel_launch(void* const* d_in, const int* in_sizes, int n_in,
                              void* d_out, int out_size) {
    const float* queries = (const float*)d_in[0];
    const float* keys    = (const float*)d_in[1];
    const float* values  = (const float*)d_in[2];
    const float* boxes   = (const float*)d_in[3];
    const float* Wq = (const float*)d_in[4];
    const float* bq = (const float*)d_in[5];
    const float* Wk = (const float*)d_in[6];
    const float* bk = (const float*)d_in[7];
    const float* Wv = (const float*)d_in[8];
    const float* bv = (const float*)d_in[9];
    const float* Wo = (const float*)d_in[10];
    const float* bo = (const float*)d_in[11];
    const float* Wg = (const float*)d_in[12];
    const float* bg = (const float*)d_in[13];
    float* out = (float*)d_out;

    cudaFuncSetAttribute(fused_attn, cudaFuncAttributeMaxDynamicSharedMemorySize,
                         FUSED_SMEM);

    boxfeat_kernel<<<16, 256>>>(boxes);
    prep_kernel<<<dim3(4096, 7), 256>>>(queries, keys, values, Wq, Wk, Wv, Wo);
    geom_kernel<<<dim3(32, 32, 8), 256>>>(Wg, bg);
    gemm_tc<0><<<dim3(8, 32, 3), 256>>>(bq, bk, bv, nullptr);
    fused_attn<<<dim3(4, 128), 256, FUSED_SMEM>>>();
    gemm_tc<1><<<dim3(8, 32, 1), 256>>>(bo, nullptr, nullptr, out);
}

// round 11
// speedup vs baseline: 2.4417x; 1.0919x over previous
#include <cuda_runtime.h>
#include <math.h>

#define BB 8
#define NN 512
#define DMODEL 1024
#define HH 16
#define DK 64

// ---- static scratch ----
__device__ float g_q[BB*HH*NN*DK];        // tf32-pre-rounded after projection
__device__ float g_k[BB*HH*NN*DK];
__device__ float g_v[BB*HH*NN*DK];
__device__ float g_s[BB*HH*NN*NN];        // geometry bias (log g), fp32
__device__ float g_o1[BB*NN*DMODEL];      // attn output, tf32-pre-rounded
__device__ float g_boxf[BB*NN*6];
__device__ float g_act[3*BB*NN*DMODEL];   // tf32-rounded activations
__device__ float g_wr[4*DMODEL*DMODEL];   // tf32-rounded weights Wq,Wk,Wv,Wo

// ---- helpers ----
__device__ __forceinline__ unsigned f2tf(float f) {
    unsigned u; asm("cvt.rna.tf32.f32 %0, %1;" : "=r"(u) : "f"(f)); return u;
}
__device__ __forceinline__ float r2(float f) { return __uint_as_float(f2tf(f)); }
__device__ __forceinline__ void mma8(float* c, const unsigned* a, const unsigned* b) {
    asm volatile("mma.sync.aligned.m16n8k8.row.col.f32.tf32.tf32.f32 "
        "{%0,%1,%2,%3},{%4,%5,%6,%7},{%8,%9},{%0,%1,%2,%3};"
        : "+f"(c[0]), "+f"(c[1]), "+f"(c[2]), "+f"(c[3])
        : "r"(a[0]), "r"(a[1]), "r"(a[2]), "r"(a[3]), "r"(b[0]), "r"(b[1]));
}
__device__ __forceinline__ void ldsm4(unsigned& r0, unsigned& r1, unsigned& r2v,
                                      unsigned& r3, unsigned a) {
    asm volatile("ldmatrix.sync.aligned.m8n8.x4.shared.b16 {%0,%1,%2,%3}, [%4];"
        : "=r"(r0), "=r"(r1), "=r"(r2v), "=r"(r3) : "r"(a));
}
__device__ __forceinline__ void cpa16(unsigned dst, const void* src) {
    asm volatile("cp.async.cg.shared.global [%0], [%1], 16;" :: "r"(dst), "l"(src));
}
__device__ __forceinline__ void cp_commit() {
    asm volatile("cp.async.commit_group;" ::: "memory");
}
__device__ __forceinline__ void cp_wait1() {
    asm volatile("cp.async.wait_group 1;" ::: "memory");
}
__device__ __forceinline__ void cp_wait0() {
    asm volatile("cp.async.wait_group 0;" ::: "memory");
}
__device__ __forceinline__ unsigned smaddr(const void* p) {
    return (unsigned)__cvta_generic_to_shared(p);
}
__device__ __forceinline__ unsigned long long pack2(float x, float y) {
    unsigned long long r; asm("mov.b64 %0,{%1,%2};" : "=l"(r) : "f"(x), "f"(y)); return r;
}
__device__ __forceinline__ void unpack2(unsigned long long v, float& x, float& y) {
    asm("mov.b64 {%0,%1},%2;" : "=f"(x), "=f"(y) : "l"(v));
}
__device__ __forceinline__ unsigned long long fma2(unsigned long long a, unsigned long long b,
                                                   unsigned long long c) {
    unsigned long long d;
    asm("fma.rn.f32x2 %0,%1,%2,%3;" : "=l"(d) : "l"(a), "l"(b), "l"(c)); return d;
}

// ============================================================
// box features
// ============================================================
__global__ void boxfeat_kernel(const float* __restrict__ boxes) {
    int i = blockIdx.x * blockDim.x + threadIdx.x;
    if (i >= BB*NN) return;
    float4 bx = ((const float4*)boxes)[i];
    float cx = 0.5f * (bx.x + bx.z);
    float cy = 0.5f * (bx.y + bx.w);
    float w  = bx.z - bx.x + 1.0f;
    float h  = bx.w - bx.y + 1.0f;
    float* o = &g_boxf[i*6];
    o[0] = cx; o[1] = cy;
    o[2] = 1.0f / w; o[3] = 1.0f / h;
    o[4] = __logf(w); o[5] = __logf(h);
}

// ============================================================
// pre-round activations + weights to tf32 (rna)
// ============================================================
__global__ void prep_kernel(const float* __restrict__ q, const float* __restrict__ k,
                            const float* __restrict__ v, const float* __restrict__ wq,
                            const float* __restrict__ wk, const float* __restrict__ wv,
                            const float* __restrict__ wo) {
    int z = blockIdx.y;
    const float* src = (z==0)?q:(z==1)?k:(z==2)?v:(z==3)?wq:(z==4)?wk:(z==5)?wv:wo;
    float* dst = (z < 3) ? g_act + (size_t)z*(BB*NN*DMODEL)
                         : g_wr + (size_t)(z-3)*(DMODEL*DMODEL);
    int n4 = (z < 3) ? (BB*NN*DMODEL/4) : (DMODEL*DMODEL/4);
    int i = blockIdx.x*256 + threadIdx.x;
    if (i < n4) {
        float4 a = ((const float4*)src)[i];
        ((uint4*)dst)[i] = make_uint4(f2tf(a.x), f2tf(a.y), f2tf(a.z), f2tf(a.w));
    }
}

// ============================================================
// geometry bias, packed f32x2 over head pairs
// ============================================================
__global__ void __launch_bounds__(256) geom_kernel(const float* __restrict__ Wg,
                                                   const float* __restrict__ bg) {
    __shared__ unsigned long long WgS2[32][8];
    __shared__ unsigned long long WgC2[32][8];
    __shared__ float qf[16][6];
    __shared__ float kf[16][6];
    __shared__ float bgs[16];
    int tid = threadIdx.x;
    int b  = blockIdx.z;
    int q0 = blockIdx.y * 16, k0 = blockIdx.x * 16;

    {
        int i = tid >> 3, p = tid & 7;
        WgS2[i][p] = pack2(Wg[(2*p)*64 + i],      Wg[(2*p+1)*64 + i]);
        WgC2[i][p] = pack2(Wg[(2*p)*64 + 32 + i], Wg[(2*p+1)*64 + 32 + i]);
    }
    if (tid < 16) {
        bgs[tid] = bg[tid];
        #pragma unroll
        for (int j = 0; j < 6; j++) qf[tid][j] = g_boxf[(b*NN + q0 + tid)*6 + j];
    } else if (tid < 32) {
        int t = tid - 16;
        #pragma unroll
        for (int j = 0; j < 6; j++) kf[t][j] = g_boxf[(b*NN + k0 + t)*6 + j];
    }
    __syncthreads();

    int ty = tid >> 4, tx = tid & 15;
    float pos[4];
    pos[0] = __logf(fmaxf(fabsf(qf[ty][0] - kf[tx][0]) * qf[ty][2], 1e-3f));
    pos[1] = __logf(fmaxf(fabsf(qf[ty][1] - kf[tx][1]) * qf[ty][3], 1e-3f));
    pos[2] = qf[ty][4] - kf[tx][4];
    pos[3] = qf[ty][5] - kf[tx][5];

    unsigned long long acc2[8];
    #pragma unroll
    for (int p = 0; p < 8; p++) acc2[p] = pack2(bgs[2*p], bgs[2*p+1]);

    const float dm[8] = {1.0f, 0.42169650f, 0.17782794f, 0.07498942f,
                         0.03162278f, 0.01333521f, 0.00562341f, 0.00237137f};
    #pragma unroll
    for (int c = 0; c < 4; c++) {
        float p100 = 100.0f * pos[c];
        #pragma unroll
        for (int f = 0; f < 8; f++) {
            float s, co;
            __sincosf(p100 * dm[f], &s, &co);
            unsigned long long s2 = pack2(s, s), c2 = pack2(co, co);
            int idx = c*8 + f;
            #pragma unroll
            for (int p = 0; p < 8; p++) {
                unsigned long long t = fma2(c2, WgC2[idx][p], acc2[p]);
                acc2[p] = fma2(s2, WgS2[idx][p], t);
            }
        }
    }
    int q = q0 + ty, k = k0 + tx;
    #pragma unroll
    for (int p = 0; p < 8; p++) {
        float x, y;
        unpack2(acc2[p], x, y);
        g_s[(((size_t)b*HH + 2*p  )*NN + q)*NN + k] = __logf(fmaxf(x, 1e-6f));
        g_s[(((size_t)b*HH + 2*p+1)*NN + q)*NN + k] = __logf(fmaxf(y, 1e-6f));
    }
}

// ============================================================
// tf32 GEMM, 128x128 CTA tile, 8 warps of 32x64, KTILE=32, 3-stage cp.async,
// LDSM fragments, no in-loop CVT (inputs pre-rounded).
// MODE 0: QKV (A=g_act[z], B=g_wr[z], rounded scatter to g_q/g_k/g_v)
// MODE 1: O-proj (A=g_o1, B=g_wr[3], dst=Cout, unrounded)
// ============================================================
#define GST 36                              // smem row stride (words) for K=32 + pad
#define GTILEW (128*GST)                    // words per matrix per stage
#define GSMEM (3 * 2 * GTILEW * 4)          // 110592 B

template<int MODE>
__global__ void __launch_bounds__(256, 2) gemm_tc(
    const float* __restrict__ b0p, const float* __restrict__ b1p,
    const float* __restrict__ b2p, float* __restrict__ Cout)
{
    constexpr int KD  = DMODEL;
    constexpr int NIT = KD / 32;            // 32 chunks
    extern __shared__ float gsm[];
    // layout: stage s: A at s*2*GTILEW, B at s*2*GTILEW + GTILEW

    int t = threadIdx.x;
    int m0 = blockIdx.y * 128, n0 = blockIdx.x * 128;
    int z = blockIdx.z;

    const float *A, *B, *bias;
    if (MODE == 0) {
        A = g_act + (size_t)z*(BB*NN*DMODEL);
        B = g_wr  + (size_t)z*(DMODEL*DMODEL);
        bias = (z == 0) ? b0p : (z == 1) ? b1p : b2p;
    } else {
        A = g_o1;
        B = g_wr + 3*(size_t)(DMODEL*DMODEL);
        bias = b0p;
    }

    // per-thread load slots: 4 chunks of A + 4 of B per stage
    int lrows[4], lc8[4];
    #pragma unroll
    for (int i = 0; i < 4; i++) {
        int idx = t + i*256;
        lrows[i] = idx >> 3;
        lc8[i]   = (idx & 7) * 4;
    }
    unsigned sbase = smaddr(gsm);

    int w = t >> 5, l = t & 31;
    int wm = w & 3, wn = w >> 2;
    int lj   = l & 7;
    int aRow = ((l >> 3) & 1) * 8 + lj;
    int aCol = (l >> 4) * 4;
    int bRow = (l >> 4) * 8 + lj;
    int bCol = ((l >> 3) & 1) * 4;

    float acc[2][8][4];
    #pragma unroll
    for (int i = 0; i < 2; i++)
        #pragma unroll
        for (int j = 0; j < 8; j++)
            #pragma unroll
            for (int k = 0; k < 4; k++) acc[i][j][k] = 0.0f;

    // prologue: chunks 0,1 -> stages 0,1
    #pragma unroll
    for (int p = 0; p < 2; p++) {
        unsigned ab = sbase + (unsigned)(p*2*GTILEW)*4u;
        #pragma unroll
        for (int i = 0; i < 4; i++) {
            cpa16(ab + (lrows[i]*GST + lc8[i])*4u,
                  A + (size_t)(m0 + lrows[i])*KD + p*32 + lc8[i]);
            cpa16(ab + (GTILEW + lrows[i]*GST + lc8[i])*4u,
                  B + (size_t)(n0 + lrows[i])*KD + p*32 + lc8[i]);
        }
        cp_commit();
    }

    for (int j = 0; j < NIT; j++) {
        cp_wait1();
        __syncthreads();
        if (j + 2 < NIT) {
            int s = (j + 2) % 3;
            unsigned ab = sbase + (unsigned)(s*2*GTILEW)*4u;
            int kb = (j + 2) * 32;
            #pragma unroll
            for (int i = 0; i < 4; i++) {
                cpa16(ab + (lrows[i]*GST + lc8[i])*4u,
                      A + (size_t)(m0 + lrows[i])*KD + kb + lc8[i]);
                cpa16(ab + (GTILEW + lrows[i]*GST + lc8[i])*4u,
                      B + (size_t)(n0 + lrows[i])*KD + kb + lc8[i]);
            }
        }
        cp_commit();

        int s = j % 3;
        const float* As = gsm + s*2*GTILEW;
        const float* Bs = As + GTILEW;
        #pragma unroll
        for (int kc = 0; kc < 4; kc++) {
            unsigned a[2][4];
            ldsm4(a[0][0], a[0][1], a[0][2], a[0][3],
                  smaddr(&As[(wm*32 + aRow)*GST + kc*8 + aCol]));
            ldsm4(a[1][0], a[1][1], a[1][2], a[1][3],
                  smaddr(&As[(wm*32 + 16 + aRow)*GST + kc*8 + aCol]));
            #pragma unroll
            for (int p = 0; p < 4; p++) {
                unsigned bb[4];
                ldsm4(bb[0], bb[1], bb[2], bb[3],
                      smaddr(&Bs[(wn*64 + p*16 + bRow)*GST + kc*8 + bCol]));
                mma8(acc[0][2*p],   a[0], bb);
                mma8(acc[0][2*p+1], a[0], bb + 2);
                mma8(acc[1][2*p],   a[1], bb);
                mma8(acc[1][2*p+1], a[1], bb + 2);
            }
        }
    }

    // epilogue
    #pragma unroll
    for (int mf = 0; mf < 2; mf++) {
        #pragma unroll
        for (int nf = 0; nf < 8; nf++) {
            int col = n0 + wn*64 + nf*8 + 2*(l & 3);
            float2 b2 = *(const float2*)(bias + col);
            #pragma unroll
            for (int rr = 0; rr < 2; rr++) {
                int row = m0 + wm*32 + mf*16 + rr*8 + (l >> 2);
                float v0 = acc[mf][nf][rr*2 + 0] + b2.x;
                float v1 = acc[mf][nf][rr*2 + 1] + b2.y;
                if (MODE == 0) {
                    int h = col >> 6, d = col & 63;
                    int bq = row >> 9, ntok = row & (NN-1);
                    float* dstp = (z == 0) ? g_q : (z == 1) ? g_k : g_v;
                    *(float2*)&dstp[(((size_t)bq*HH + h)*NN + ntok)*DK + d] =
                        make_float2(r2(v0), r2(v1));
                } else {
                    *(float2*)&Cout[(size_t)row*DMODEL + col] = make_float2(v0, v1);
                }
            }
        }
    }
}

// ============================================================
// fused attention: S = bias + (Q/8)Kt, online softmax, O += P V
// (unchanged from R10)
// ============================================================
#define KS_ST 68
#define VS_ST 72
#define PS_ST 68
#define FUSED_SMEM ((2*64*KS_ST + 2*64*VS_ST + 128*PS_ST) * 4)

__global__ void __launch_bounds__(256, 2) fused_attn() {
    extern __shared__ float smf[];
    float* KsB = smf;
    float* VsB = smf + 2*64*KS_ST;
    float* Ps  = VsB + 2*64*VS_ST;

    int t = threadIdx.x;
    int bh = blockIdx.y;
    int q0 = blockIdx.x * 128;
    const float* Qg = g_q + ((size_t)bh*NN + q0)*DK;
    const float* Kg = g_k + (size_t)bh*NN*DK;
    const float* Vg = g_v + (size_t)bh*NN*DK;
    const float* Sg = g_s + (size_t)bh*NN*NN;

    int w = t >> 5, l = t & 31;
    int r0 = l >> 2, c0 = l & 3;
    int qrow = w*16 + r0;
    int lj   = l & 7;
    int aRow = ((l >> 3) & 1) * 8 + lj;
    int aCol = (l >> 4) * 4;
    int bRow = (l >> 4) * 8 + lj;
    int bCol = ((l >> 3) & 1) * 4;

    #pragma unroll
    for (int i = 0; i < 8; i++) {
        int idx = t + i*256;
        int row = idx >> 4, col = (idx & 15) * 4;
        cpa16(smaddr(Ps + row*PS_ST + col), Qg + row*DK + col);
    }
    #pragma unroll
    for (int i = 0; i < 4; i++) {
        int idx = t + i*256;
        int row = idx >> 4, col = (idx & 15) * 4;
        cpa16(smaddr(KsB + row*KS_ST + col), Kg + row*DK + col);
        cpa16(smaddr(VsB + row*VS_ST + col), Vg + row*DK + col);
    }
    cp_commit();
    cp_wait0();
    __syncthreads();

    unsigned qa[8][4];
    #pragma unroll
    for (int kc = 0; kc < 8; kc++) {
        qa[kc][0] = __float_as_uint(0.125f * Ps[qrow*PS_ST     + kc*8 + c0]);
        qa[kc][1] = __float_as_uint(0.125f * Ps[(qrow+8)*PS_ST + kc*8 + c0]);
        qa[kc][2] = __float_as_uint(0.125f * Ps[qrow*PS_ST     + kc*8 + c0 + 4]);
        qa[kc][3] = __float_as_uint(0.125f * Ps[(qrow+8)*PS_ST + kc*8 + c0 + 4]);
    }

    float Oa[8][4];
    #pragma unroll
    for (int nf = 0; nf < 8; nf++)
        #pragma unroll
        for (int k = 0; k < 4; k++) Oa[nf][k] = 0.0f;
    float m0v = -INFINITY, m1v = -INFINITY, l0v = 0.0f, l1v = 0.0f;

    const int NT = NN / 64;
    for (int j = 0; j < NT; j++) {
        if (j > 0) cp_wait0();
        __syncthreads();
        if (j + 1 < NT) {
            int nb = (j + 1) & 1;
            float* Ksn = KsB + nb*64*KS_ST;
            float* Vsn = VsB + nb*64*VS_ST;
            #pragma unroll
            for (int i = 0; i < 4; i++) {
                int idx = t + i*256;
                int row = idx >> 4, col = (idx & 15) * 4;
                cpa16(smaddr(Ksn + row*KS_ST + col), Kg + ((j+1)*64 + row)*DK + col);
                cpa16(smaddr(Vsn + row*VS_ST + col), Vg + ((j+1)*64 + row)*DK + col);
            }
        }
        cp_commit();

        const float* Ks = KsB + (j & 1)*64*KS_ST;
        const float* Vs = VsB + (j & 1)*64*VS_ST;

        float acc[8][4];
        {
            const float* br0 = Sg + (size_t)(q0 + qrow)*NN + j*64;
            const float* br1 = br0 + 8*NN;
            #pragma unroll
            for (int nf = 0; nf < 8; nf++) {
                float2 t0 = *(const float2*)(br0 + nf*8 + 2*c0);
                float2 t1 = *(const float2*)(br1 + nf*8 + 2*c0);
                acc[nf][0] = t0.x; acc[nf][1] = t0.y;
                acc[nf][2] = t1.x; acc[nf][3] = t1.y;
            }
        }
        #pragma unroll
        for (int kc = 0; kc < 8; kc++) {
            #pragma unroll
            for (int p = 0; p < 4; p++) {
                unsigned bb[4];
                ldsm4(bb[0], bb[1], bb[2], bb[3],
                      smaddr(&Ks[(p*16 + bRow)*KS_ST + kc*8 + bCol]));
                mma8(acc[2*p],   qa[kc], bb);
                mma8(acc[2*p+1], qa[kc], bb + 2);
            }
        }

        float mx0 = -INFINITY, mx1 = -INFINITY;
        #pragma unroll
        for (int nf = 0; nf < 8; nf++) {
            mx0 = fmaxf(mx0, fmaxf(acc[nf][0], acc[nf][1]));
            mx1 = fmaxf(mx1, fmaxf(acc[nf][2], acc[nf][3]));
        }
        #pragma unroll
        for (int o = 1; o <= 2; o <<= 1) {
            mx0 = fmaxf(mx0, __shfl_xor_sync(0xffffffffu, mx0, o));
            mx1 = fmaxf(mx1, __shfl_xor_sync(0xffffffffu, mx1, o));
        }
        float mn0 = fmaxf(m0v, mx0), mn1 = fmaxf(m1v, mx1);
        float sc0 = __expf(m0v - mn0), sc1 = __expf(m1v - mn1);
        m0v = mn0; m1v = mn1;
        float s0 = 0.0f, s1 = 0.0f;
        #pragma unroll
        for (int nf = 0; nf < 8; nf++) {
            acc[nf][0] = __expf(acc[nf][0] - mn0);
            acc[nf][1] = __expf(acc[nf][1] - mn0);
            acc[nf][2] = __expf(acc[nf][2] - mn1);
            acc[nf][3] = __expf(acc[nf][3] - mn1);
            s0 += acc[nf][0] + acc[nf][1];
            s1 += acc[nf][2] + acc[nf][3];
        }
        #pragma unroll
        for (int o = 1; o <= 2; o <<= 1) {
            s0 += __shfl_xor_sync(0xffffffffu, s0, o);
            s1 += __shfl_xor_sync(0xffffffffu, s1, o);
        }
        l0v = l0v * sc0 + s0;
        l1v = l1v * sc1 + s1;
        #pragma unroll
        for (int nf = 0; nf < 8; nf++) {
            Oa[nf][0] *= sc0; Oa[nf][1] *= sc0;
            Oa[nf][2] *= sc1; Oa[nf][3] *= sc1;
        }

        #pragma unroll
        for (int nf = 0; nf < 8; nf++) {
            *(float2*)&Ps[qrow*PS_ST     + nf*8 + 2*c0] =
                make_float2(r2(acc[nf][0]), r2(acc[nf][1]));
            *(float2*)&Ps[(qrow+8)*PS_ST + nf*8 + 2*c0] =
                make_float2(r2(acc[nf][2]), r2(acc[nf][3]));
        }
        __syncwarp();
        #pragma unroll
        for (int kc = 0; kc < 8; kc++) {
            unsigned a4[4];
            ldsm4(a4[0], a4[1], a4[2], a4[3],
                  smaddr(&Ps[(w*16 + aRow)*PS_ST + kc*8 + aCol]));
            #pragma unroll
            for (int nf = 0; nf < 8; nf++) {
                unsigned b[2];
                b[0] = __float_as_uint(Vs[(kc*8 + c0    )*VS_ST + r0 + nf*8]);
                b[1] = __float_as_uint(Vs[(kc*8 + c0 + 4)*VS_ST + r0 + nf*8]);
                mma8(Oa[nf], a4, b);
            }
        }
        __syncwarp();
    }

    float inv0 = 1.0f / l0v, inv1 = 1.0f / l1v;
    int b = bh >> 4, h = bh & 15;
    float* O0 = g_o1 + ((size_t)b*NN + q0 + qrow)*DMODEL + h*DK;
    float* O1 = O0 + 8*DMODEL;
    #pragma unroll
    for (int nf = 0; nf < 8; nf++) {
        *(float2*)(O0 + nf*8 + 2*c0) =
            make_float2(r2(Oa[nf][0]*inv0), r2(Oa[nf][1]*inv0));
        *(float2*)(O1 + nf*8 + 2*c0) =
            make_float2(r2(Oa[nf][2]*inv1), r2(Oa[nf][3]*inv1));
    }
}

// ============================================================
extern "C" void kernel_launch(void* const* d_in, const int* in_sizes, int n_in,
                              void* d_out, int out_size) {
    const float* queries = (const float*)d_in[0];
    const float* keys    = (const float*)d_in[1];
    const float* values  = (const float*)d_in[2];
    const float* boxes   = (const float*)d_in[3];
    const float* Wq = (const float*)d_in[4];
    const float* bq = (const float*)d_in[5];
    const float* Wk = (const float*)d_in[6];
    const float* bk = (const float*)d_in[7];
    const float* Wv = (const float*)d_in[8];
    const float* bv = (const float*)d_in[9];
    const float* Wo = (const float*)d_in[10];
    const float* bo = (const float*)d_in[11];
    const float* Wg = (const float*)d_in[12];
    const float* bg = (const float*)d_in[13];
    float* out = (float*)d_out;

    cudaFuncSetAttribute(gemm_tc<0>, cudaFuncAttributeMaxDynamicSharedMemorySize, GSMEM);
    cudaFuncSetAttribute(gemm_tc<1>, cudaFuncAttributeMaxDynamicSharedMemorySize, GSMEM);
    cudaFuncSetAttribute(fused_attn, cudaFuncAttributeMaxDynamicSharedMemorySize,
                         FUSED_SMEM);

    boxfeat_kernel<<<16, 256>>>(boxes);
    prep_kernel<<<dim3(4096, 7), 256>>>(queries, keys, values, Wq, Wk, Wv, Wo);
    geom_kernel<<<dim3(32, 32, 8), 256>>>(Wg, bg);
    gemm_tc<0><<<dim3(8, 32, 3), 256, GSMEM>>>(bq, bk, bv, nullptr);
    fused_attn<<<dim3(4, 128), 256, FUSED_SMEM>>>();
    gemm_tc<1><<<dim3(8, 32, 1), 256, GSMEM>>>(bo, nullptr, nullptr, out);
}